// round 5
// baseline (speedup 1.0000x reference)
#include <cuda_runtime.h>
#include <math.h>

// ---------------- problem constants ----------------
#define BG   256
#define NPG  256
#define NN   (BG*NPG)            // 65536 nodes
#define EE   (NN*16)             // 1048576 edges
#define KK   25
#define F1   32
#define F2   64
#define F3   128
#define NC1  (BG*64)             // 16384 pool-1 clusters
#define NC2  (BG*16)             // 4096  pool-2 clusters
#define BM1W (BG*4096/32)
#define BM2W (BG*256/32)
#define E3CAP 65536
#define NBKT (BG*8)              // 2048 (graph, row-octile) buckets
#define BCAP 512                 // max edges/bucket (8 rows x 63 targets = 504)
#define B3SZ (BG*KK*16*16)

// ---------------- device scratch ----------------
__device__ float    d_m[4];
__device__ int      d_ecnt1[1];
__device__ int      d_ecnt2[1];
__device__ float    d_acc1[NN*32];          // 25 basis + slot25 = degree
__device__ float    d_x2[NC1*F1];
__device__ float    d_cnt1[NC1];
__device__ float    d_pos2[NC1*2];
__device__ int      d_er2[EE];
__device__ int      d_ec2[EE];
__device__ unsigned d_bm1[BM1W];
__device__ int      d_bcnt[NBKT];
__device__ uint4    d_bkt[NBKT*BCAP];
__device__ float    d_acc2[(size_t)NC1*KK*F1];   // pre-divided by deg
__device__ float    d_x3[NC2*F2];
__device__ float    d_cnt2[NC2];
__device__ float    d_pos3[NC2*2];
__device__ int      d_er3[E3CAP];
__device__ int      d_ec3[E3CAP];
__device__ unsigned d_bm2[BM2W];
__device__ float    d_B3[B3SZ];
__device__ float    d_acc3[NC2*KK*F2];           // pre-divided by deg
__device__ float    d_deg3[NC2];
__device__ float    d_h3[NC2*F3];

// ---------------- helpers ----------------
__device__ __forceinline__ float eluf(float v){ return v > 0.f ? v : expm1f(v); }

__device__ __forceinline__ void atomicMaxF(float* a, float v){
    if (v >= 0.f) atomicMax((int*)a, __float_as_int(v));
    else          atomicMin((unsigned int*)a, __float_as_uint(v));
}

__device__ __forceinline__ void warpMaxAtomic(float mx, float* dst){
    #pragma unroll
    for (int o = 16; o; o >>= 1) mx = fmaxf(mx, __shfl_xor_sync(0xffffffffu, mx, o));
    if ((threadIdx.x & 31) == 0) atomicMax((int*)dst, __float_as_int(mx));
}

__device__ __forceinline__ void spline_corners(float psx, float psy,
                                               int& ix, int& iy, float& fx, float& fy){
    float vx = psx * 4.f, vy = psy * 4.f;
    float fix = fminf(fmaxf(floorf(vx), 0.f), 3.f);
    float fiy = fminf(fmaxf(floorf(vy), 0.f), 3.f);
    fx = vx - fix; fy = vy - fiy;
    ix = (int)fix; iy = (int)fiy;
}

__device__ __forceinline__ int cell1(float px, float py){
    int cx = min(max((int)floorf(px * 0.25f), 0), 7);
    int cy = min(max((int)floorf(py * 0.25f), 0), 7);
    return cx * 8 + cy;
}
__device__ __forceinline__ int clu2_of(int j){
    float px = d_pos2[2*j], py = d_pos2[2*j+1];
    int cx = min(max((int)floorf(px * 0.125f), 0), 3);
    int cy = min(max((int)floorf(py * 0.125f), 0), 3);
    return (j >> 6) * 16 + cx * 4 + cy;
}

// f32x2 packed FMA helpers
__device__ __forceinline__ unsigned long long splat2(float x){
    unsigned long long r;
    asm("mov.b64 %0, {%1, %1};" : "=l"(r) : "f"(x));
    return r;
}
__device__ __forceinline__ unsigned long long pack2(float lo, float hi){
    unsigned long long r;
    asm("mov.b64 %0, {%1, %2};" : "=l"(r) : "f"(lo), "f"(hi));
    return r;
}
__device__ __forceinline__ void ffma2(unsigned long long& d,
                                      unsigned long long a, unsigned long long b){
    asm("fma.rn.f32x2 %0, %1, %2, %0;" : "+l"(d) : "l"(a), "l"(b));
}
__device__ __forceinline__ float f2lo(unsigned long long u){ return __uint_as_float((unsigned)u); }
__device__ __forceinline__ float f2hi(unsigned long long u){ return __uint_as_float((unsigned)(u>>32)); }

// ---------------- init (small now: no dense B2) ----------------
__global__ void k_init(){
    long t = (long)blockIdx.x * blockDim.x + threadIdx.x;
    long S = (long)gridDim.x * blockDim.x;
    const float NEG = -3.4e38f;
    float4 z4 = make_float4(0.f,0.f,0.f,0.f);
    float4 n4 = make_float4(NEG,NEG,NEG,NEG);
    for (long i=t;i<(long)NN*32/4;i+=S) ((float4*)d_acc1)[i]=z4;
    for (long i=t;i<B3SZ/4;       i+=S) ((float4*)d_B3)[i]=z4;
    for (long i=t;i<NC1*F1/4;     i+=S) ((float4*)d_x2)[i]=n4;
    for (long i=t;i<NC2*F2/4;     i+=S) ((float4*)d_x3)[i]=n4;
    for (long i=t;i<NC1;          i+=S) d_cnt1[i]=0.f;
    for (long i=t;i<NC2;          i+=S){ d_deg3[i]=0.f; d_cnt2[i]=0.f; }
    for (long i=t;i<NC1*2;        i+=S) d_pos2[i]=0.f;
    for (long i=t;i<NC2*2;        i+=S) d_pos3[i]=0.f;
    for (long i=t;i<BM1W;         i+=S) d_bm1[i]=0u;
    for (long i=t;i<BM2W;         i+=S) d_bm2[i]=0u;
    for (long i=t;i<NBKT;         i+=S) d_bcnt[i]=0;
    if (t==0){ d_ecnt1[0]=0; d_ecnt2[0]=0; d_m[0]=d_m[1]=d_m[2]=0.f; }
}

// ---------------- layer 1 ----------------
__global__ void k_m1(const float* __restrict__ pos, const int* __restrict__ row,
                     const int* __restrict__ col){
    const float2* p2 = (const float2*)pos;
    float mx = 0.f;
    for (int e = blockIdx.x*blockDim.x + threadIdx.x; e < EE; e += gridDim.x*blockDim.x){
        float2 pr = p2[row[e]], pc = p2[col[e]];
        mx = fmaxf(mx, fmaxf(fabsf(pc.x - pr.x), fabsf(pc.y - pr.y)));
    }
    warpMaxAtomic(mx, &d_m[0]);
}

// fused: basis scatter (acc1 + degree) AND level-2 edge dedup/append
__global__ void k_scatter_remap1(const float* __restrict__ pos, const float* __restrict__ x,
                                 const int* __restrict__ row, const int* __restrict__ col){
    const float2* p2 = (const float2*)pos;
    int e = blockIdx.x*blockDim.x + threadIdx.x;   // grid sized exactly EE
    int r = row[e], c = col[e];
    float2 pr = p2[r], pc = p2[c];
    float inv = 1.f / (2.f * d_m[0] + 1e-12f);
    float psx = (pc.x - pr.x) * inv + 0.5f;
    float psy = (pc.y - pr.y) * inv + 0.5f;
    int ix, iy; float fx, fy;
    spline_corners(psx, psy, ix, iy, fx, fy);
    float xin = x[c];
    float wxs[2] = {1.f-fx, fx}, wys[2] = {1.f-fy, fy};
    #pragma unroll
    for (int sx=0; sx<2; sx++)
        #pragma unroll
        for (int sy=0; sy<2; sy++)
            atomicAdd(&d_acc1[r*32 + (ix+sx)*5 + (iy+sy)], wxs[sx]*wys[sy]*xin);
    atomicAdd(&d_acc1[r*32 + 25], 1.f);

    // remap to level-2 clusters + dedup
    int r2 = (r >> 8) * 64 + cell1(pr.x, pr.y);
    int c2 = (c >> 8) * 64 + cell1(pc.x, pc.y);
    bool newe = false;
    if (r2 != c2){
        int key = ((r2 >> 6) << 12) | ((r2 & 63) << 6) | (c2 & 63);
        unsigned bit = 1u << (key & 31);
        unsigned old = atomicOr(&d_bm1[key >> 5], bit);
        newe = !(old & bit);
    }
    unsigned mball = __ballot_sync(0xffffffffu, newe);
    if (!mball) return;
    int lane = threadIdx.x & 31;
    int leader = __ffs(mball) - 1;
    int base = 0;
    if (lane == leader) base = atomicAdd(&d_ecnt1[0], __popc(mball));
    base = __shfl_sync(0xffffffffu, base, leader);
    if (newe){
        int ofs = __popc(mball & ((1u << lane) - 1u));
        d_er2[base + ofs] = r2;
        d_ec2[base + ofs] = c2;
    }
}

// fused node transform (layer 1) + grid pool 1 (no h1 buffer)
__global__ void k_node1pool1(const float* __restrict__ x, const float* __restrict__ W1,
                             const float* __restrict__ r1, const float* __restrict__ b1,
                             const float* __restrict__ pos){
    __shared__ float sW[KK*F1], sr[F1], sb[F1];
    for (int i = threadIdx.x; i < KK*F1; i += blockDim.x) sW[i] = W1[i];
    if (threadIdx.x < F1){ sr[threadIdx.x] = r1[threadIdx.x]; sb[threadIdx.x] = b1[threadIdx.x]; }
    __syncthreads();
    int n = blockIdx.x * 8 + (threadIdx.x >> 5);
    int o = threadIdx.x & 31;
    float s = 0.f;
    #pragma unroll
    for (int k4 = 0; k4 < 24; k4 += 4){
        float4 a = *(const float4*)&d_acc1[n*32 + k4];
        s += a.x * sW[(k4+0)*F1 + o];
        s += a.y * sW[(k4+1)*F1 + o];
        s += a.z * sW[(k4+2)*F1 + o];
        s += a.w * sW[(k4+3)*F1 + o];
    }
    s += d_acc1[n*32 + 24] * sW[24*F1 + o];
    float dg = fmaxf(d_acc1[n*32 + 25], 1.f);
    float2 p = ((const float2*)pos)[n];
    float h = eluf(s / dg + x[n] * sr[o] + sb[o]);
    int cl = (n >> 8) * 64 + cell1(p.x, p.y);
    atomicMaxF(&d_x2[cl*F1 + o], h);
    if (o == 0){
        atomicAdd(&d_cnt1[cl], 1.f);
        atomicAdd(&d_pos2[2*cl],   p.x);
        atomicAdd(&d_pos2[2*cl+1], p.y);
    }
}

__global__ void k_fin1(){
    int t = blockIdx.x*blockDim.x + threadIdx.x;
    if (t >= NC1*F1) return;
    int cl = t / F1, f = t % F1;
    float cnt = d_cnt1[cl];
    if (f < 2) d_pos2[2*cl + f] *= 1.f / fmaxf(cnt, 1.f);
    if (cnt <= 0.f) d_x2[t] = 0.f;
}

// per pool-1-node contribution to pool-2 cluster meta (cnt2, pos3 sums)
__global__ void k_pool2meta(){
    int w = blockIdx.x*blockDim.x + threadIdx.x;
    if (w >= NC1) return;
    if (d_cnt1[w] <= 0.f) return;
    float px = d_pos2[2*w], py = d_pos2[2*w+1];
    int cl = clu2_of(w);
    atomicAdd(&d_cnt2[cl], 1.f);
    atomicAdd(&d_pos3[2*cl],   px);
    atomicAdd(&d_pos3[2*cl+1], py);
}

// build unique level-3 edges from level-2 list
__global__ void k_remap2(){
    int nE = d_ecnt1[0];
    int lane = threadIdx.x & 31;
    int gw   = (blockIdx.x*blockDim.x + threadIdx.x) >> 5;
    int nW   = (gridDim.x*blockDim.x) >> 5;
    for (int b = gw*32; b < nE; b += nW*32){
        int e = b + lane;
        bool newe = false; int r3 = 0, c3 = 0;
        if (e < nE){
            r3 = clu2_of(d_er2[e]);
            c3 = clu2_of(d_ec2[e]);
            if (r3 != c3){
                int key = ((r3 >> 4) << 8) | ((r3 & 15) << 4) | (c3 & 15);
                unsigned bit = 1u << (key & 31);
                unsigned old = atomicOr(&d_bm2[key >> 5], bit);
                newe = !(old & bit);
            }
        }
        unsigned mball = __ballot_sync(0xffffffffu, newe);
        if (!mball) continue;
        int leader = __ffs(mball) - 1;
        int base = 0;
        if (lane == leader) base = atomicAdd(&d_ecnt2[0], __popc(mball));
        base = __shfl_sync(0xffffffffu, base, leader);
        if (newe){
            int ofs = __popc(mball & ((1u << lane) - 1u));
            d_er3[base + ofs] = r3;
            d_ec3[base + ofs] = c3;
        }
    }
}

__global__ void k_m2(){
    int nE = d_ecnt1[0];
    float mx = 0.f;
    for (int e = blockIdx.x*blockDim.x + threadIdx.x; e < nE; e += gridDim.x*blockDim.x){
        int r = d_er2[e], c = d_ec2[e];
        float dx = d_pos2[2*c]   - d_pos2[2*r];
        float dy = d_pos2[2*c+1] - d_pos2[2*r+1];
        mx = fmaxf(mx, fmaxf(fabsf(dx), fabsf(dy)));
    }
    warpMaxAtomic(mx, &d_m[1]);
}

// distribute unique level-2 edges into (graph, row-octile) buckets with weights
__global__ void k_fillBuckets(){
    int nE = d_ecnt1[0];
    float inv = 1.f / (2.f * d_m[1] + 1e-12f);
    for (int e = blockIdx.x*blockDim.x + threadIdx.x; e < nE; e += gridDim.x*blockDim.x){
        int r = d_er2[e], c = d_ec2[e];
        float psx = (d_pos2[2*c]   - d_pos2[2*r])   * inv + 0.5f;
        float psy = (d_pos2[2*c+1] - d_pos2[2*r+1]) * inv + 0.5f;
        int ix, iy; float fx, fy;
        spline_corners(psx, psy, ix, iy, fx, fy);
        int rl = r & 63, cl = c & 63, g = r >> 6;
        int bucket = g*8 + (rl >> 3);
        int slot = atomicAdd(&d_bcnt[bucket], 1);
        unsigned meta = (unsigned)rl | ((unsigned)cl << 6) | ((unsigned)ix << 12) | ((unsigned)iy << 14);
        d_bkt[bucket*BCAP + slot] = make_uint4(meta, __float_as_uint(fx), __float_as_uint(fy), 0u);
    }
}

// acc2[g, oct*8+r, k, i] accumulated in SMEM per single-warp block; pre-divided by deg
__global__ void k_acc2(){
    __shared__ float acc_s[8*KK*F1];     // 25.6 KB
    __shared__ float xs[64*F1];          // 8 KB
    __shared__ float scnt[8];
    int g = blockIdx.x >> 3, oct = blockIdx.x & 7;
    int lane = threadIdx.x;              // 32 threads

    #pragma unroll
    for (int i = lane*4; i < 8*KK*F1; i += 128) *(float4*)&acc_s[i] = make_float4(0,0,0,0);
    for (int i = lane*4; i < 64*F1; i += 128)
        *(float4*)&xs[i] = *(const float4*)&d_x2[g*64*F1 + i];
    if (lane < 8) scnt[lane] = 0.f;
    __syncwarp();

    int nE = d_bcnt[blockIdx.x];
    const uint4* bk = &d_bkt[blockIdx.x*BCAP];
    for (int e = 0; e < nE; e++){
        uint4 ed = bk[e];
        unsigned meta = ed.x;
        int rl = meta & 63, cl = (meta >> 6) & 63;
        int ix = (meta >> 12) & 3, iy = (meta >> 14) & 3;
        float fx = __uint_as_float(ed.y), fy = __uint_as_float(ed.z);
        float xv = xs[cl*F1 + lane];
        int rbase = (rl & 7) * (KK*F1);
        int kb = ix*5 + iy;
        float w00 = (1.f-fx)*(1.f-fy), w01 = (1.f-fx)*fy;
        float w10 = fx*(1.f-fy),       w11 = fx*fy;
        acc_s[rbase + (kb  )*F1 + lane] += w00 * xv;
        acc_s[rbase + (kb+1)*F1 + lane] += w01 * xv;
        acc_s[rbase + (kb+5)*F1 + lane] += w10 * xv;
        acc_s[rbase + (kb+6)*F1 + lane] += w11 * xv;
        if (lane == 0) scnt[rl & 7] += 1.f;
    }
    __syncwarp();

    #pragma unroll
    for (int r = 0; r < 8; r++){
        float invd = 1.f / fmaxf(scnt[r], 1.f);
        size_t rowbase = (size_t)(g*64 + oct*8 + r) * (KK*F1);
        #pragma unroll
        for (int k = 0; k < KK; k++)
            d_acc2[rowbase + k*F1 + lane] = acc_s[r*(KK*F1) + k*F1 + lane] * invd;
    }
}

// ---------------- 64-thread GEMM: OUT = A@W + XIN@ROOT + BIAS, optional pool fusion ----------------
// A pre-divided by degree. Thread tile RPT rows x 8 cols (f32x2 pairs).
template<int BM, int RPT, int KDIM, int FIN, int NOUT, bool POOL>
__device__ __forceinline__ void gemm64_body(
    const float* __restrict__ A, const float* __restrict__ W,
    const float* __restrict__ XIN, const float* __restrict__ ROOT,
    const float* __restrict__ BIAS, float* __restrict__ OUT)
{
    const int BK = 16;
    __shared__ float As[BK][BM + 4];
    __shared__ float Bs[BK][64];
    int bm = blockIdx.x * BM;
    int bn = blockIdx.y * 64;
    int t  = threadIdx.x;            // 64
    int tx = t & 7, ty = t >> 3;
    unsigned long long acc[RPT][4];
    #pragma unroll
    for (int r=0;r<RPT;r++)
        #pragma unroll
        for (int j=0;j<4;j++) acc[r][j]=0ull;

    const int KTOT = KDIM + FIN;
    for (int kk = 0; kk < KTOT; kk += BK){
        bool ext = (kk >= KDIM);
        const float* srcA = ext ? XIN : A;
        const float* srcB = ext ? ROOT : W;
        int ld   = ext ? FIN : KDIM;
        int kofs = ext ? (kk - KDIM) : kk;
        #pragma unroll
        for (int w = 0; w < BM/16; w++){
            int fidx = t + w*64;
            int m = fidx >> 2, k4 = (fidx & 3)*4;
            float4 v = *(const float4*)&srcA[(size_t)(bm+m)*ld + kofs + k4];
            As[k4+0][m]=v.x; As[k4+1][m]=v.y; As[k4+2][m]=v.z; As[k4+3][m]=v.w;
        }
        #pragma unroll
        for (int w = 0; w < 4; w++){
            int fidx = t + w*64;
            int kb = fidx >> 4, n4 = (fidx & 15)*4;
            *(float4*)&Bs[kb][n4] = *(const float4*)&srcB[(size_t)(kofs+kb)*NOUT + bn + n4];
        }
        __syncthreads();
        #pragma unroll
        for (int kb = 0; kb < BK; kb++){
            float a[RPT];
            #pragma unroll
            for (int q = 0; q < RPT/4; q++)
                *(float4*)&a[q*4] = *(const float4*)&As[kb][ty*RPT + q*4];
            float4 b0 = *(const float4*)&Bs[kb][tx*8];
            float4 b1 = *(const float4*)&Bs[kb][tx*8 + 4];
            unsigned long long bp[4] = { pack2(b0.x,b0.y), pack2(b0.z,b0.w),
                                         pack2(b1.x,b1.y), pack2(b1.z,b1.w) };
            #pragma unroll
            for (int r = 0; r < RPT; r++){
                unsigned long long as = splat2(a[r]);
                ffma2(acc[r][0], as, bp[0]);
                ffma2(acc[r][1], as, bp[1]);
                ffma2(acc[r][2], as, bp[2]);
                ffma2(acc[r][3], as, bp[3]);
            }
        }
        __syncthreads();
    }
    #pragma unroll
    for (int r = 0; r < RPT; r++){
        int m = bm + ty*RPT + r;
        if (POOL){
            if (d_cnt1[m] <= 0.f) continue;
            int cl = clu2_of(m);
            #pragma unroll
            for (int j = 0; j < 4; j++){
                int o = bn + tx*8 + 2*j;
                float h0 = eluf(f2lo(acc[r][j]) + BIAS[o]);
                float h1 = eluf(f2hi(acc[r][j]) + BIAS[o+1]);
                atomicMaxF(&d_x3[cl*F2 + o],     h0);
                atomicMaxF(&d_x3[cl*F2 + o + 1], h1);
            }
        } else {
            float4 o0, o1;
            int ob = bn + tx*8;
            o0.x = eluf(f2lo(acc[r][0]) + BIAS[ob+0]);
            o0.y = eluf(f2hi(acc[r][0]) + BIAS[ob+1]);
            o0.z = eluf(f2lo(acc[r][1]) + BIAS[ob+2]);
            o0.w = eluf(f2hi(acc[r][1]) + BIAS[ob+3]);
            o1.x = eluf(f2lo(acc[r][2]) + BIAS[ob+4]);
            o1.y = eluf(f2hi(acc[r][2]) + BIAS[ob+5]);
            o1.z = eluf(f2lo(acc[r][3]) + BIAS[ob+6]);
            o1.w = eluf(f2hi(acc[r][3]) + BIAS[ob+7]);
            *(float4*)&OUT[(size_t)m*NOUT + ob]     = o0;
            *(float4*)&OUT[(size_t)m*NOUT + ob + 4] = o1;
        }
    }
}

__global__ void k_gemm2pool(const float* __restrict__ W, const float* __restrict__ ROOT,
                            const float* __restrict__ BIAS){
    gemm64_body<64, 8, KK*F1, F1, F2, true>(d_acc2, W, d_x2, ROOT, BIAS, nullptr);
}
__global__ void k_gemm3(const float* __restrict__ W, const float* __restrict__ ROOT,
                        const float* __restrict__ BIAS){
    gemm64_body<64, 8, KK*F2, F2, F3, false>(d_acc3, W, d_x3, ROOT, BIAS, d_h3);
}

__global__ void k_fin2(){
    int t = blockIdx.x*blockDim.x + threadIdx.x;
    if (t >= NC2*F2) return;
    int cl = t / F2, f = t % F2;
    float cnt = d_cnt2[cl];
    if (f < 2) d_pos3[2*cl + f] *= 1.f / fmaxf(cnt, 1.f);
    if (cnt <= 0.f) d_x3[t] = 0.f;
}

// ---------------- layer 3 ----------------
__global__ void k_m3(){
    int nE = d_ecnt2[0];
    float mx = 0.f;
    for (int e = blockIdx.x*blockDim.x + threadIdx.x; e < nE; e += gridDim.x*blockDim.x){
        int r = d_er3[e], c = d_ec3[e];
        float dx = d_pos3[2*c]   - d_pos3[2*r];
        float dy = d_pos3[2*c+1] - d_pos3[2*r+1];
        mx = fmaxf(mx, fmaxf(fabsf(dx), fabsf(dy)));
    }
    warpMaxAtomic(mx, &d_m[2]);
}

__global__ void k_fillB3(){
    int nE = d_ecnt2[0];
    float inv = 1.f / (2.f * d_m[2] + 1e-12f);
    for (int e = blockIdx.x*blockDim.x + threadIdx.x; e < nE; e += gridDim.x*blockDim.x){
        int r = d_er3[e], c = d_ec3[e];
        int g = r >> 4;
        float psx = (d_pos3[2*c]   - d_pos3[2*r])   * inv + 0.5f;
        float psy = (d_pos3[2*c+1] - d_pos3[2*r+1]) * inv + 0.5f;
        int ix, iy; float fx, fy;
        spline_corners(psx, psy, ix, iy, fx, fy);
        float wxs[2] = {1.f-fx, fx}, wys[2] = {1.f-fy, fy};
        int rl = r & 15, cl = c & 15;
        #pragma unroll
        for (int sx=0; sx<2; sx++)
            #pragma unroll
            for (int sy=0; sy<2; sy++){
                int idx = (ix+sx)*5 + (iy+sy);
                d_B3[((g*KK + idx)*16 + rl)*16 + cl] = wxs[sx]*wys[sy];
            }
        atomicAdd(&d_deg3[r], 1.f);
    }
}

// acc3[g,r,k,i] = (1/deg) * sum_c B3[g,k,r,c] * x3[g,c,i]; also re-zeroes B3 tile
__global__ void k_bgemm3(){
    __shared__ float Bs3[16][17];
    __shared__ float xs3[16][64];
    int g = blockIdx.x / KK;
    int k = blockIdx.x % KK;
    size_t bbase = (size_t)blockIdx.x * 256;
    int t = threadIdx.x;
    if (t < 64){
        int r = t >> 2, c4 = (t & 3) * 4;
        float4 v = *(const float4*)&d_B3[bbase + r*16 + c4];
        Bs3[r][c4+0]=v.x; Bs3[r][c4+1]=v.y; Bs3[r][c4+2]=v.z; Bs3[r][c4+3]=v.w;
        *(float4*)&d_B3[bbase + r*16 + c4] = make_float4(0,0,0,0);  // restore zero
    }
    {
        int c = t >> 4, i4 = (t & 15) * 4;
        *(float4*)&xs3[c][i4] = *(const float4*)&d_x3[(g*16 + c)*F2 + i4];
    }
    __syncthreads();
    int r = t >> 4, i4 = (t & 15) * 4;
    float4 acc = make_float4(0.f,0.f,0.f,0.f);
    #pragma unroll
    for (int c = 0; c < 16; c++){
        float b = Bs3[r][c];
        float4 xv = *(const float4*)&xs3[c][i4];
        acc.x += b*xv.x; acc.y += b*xv.y; acc.z += b*xv.z; acc.w += b*xv.w;
    }
    float invd = 1.f / fmaxf(d_deg3[g*16 + r], 1.f);
    acc.x *= invd; acc.y *= invd; acc.z *= invd; acc.w *= invd;
    *(float4*)&d_acc3[((size_t)(g*16 + r))*(KK*F2) + k*F2 + i4] = acc;
}

// ---------------- readout ----------------
__global__ void k_readout(const float* __restrict__ fcw, const float* __restrict__ fcb,
                          float* __restrict__ out){
    int g = blockIdx.x, t = threadIdx.x;     // 128 threads
    __shared__ float sf[F3];
    __shared__ float slg[10];
    float s = 0.f, cnt = 0.f;
    for (int j = 0; j < 16; j++){
        int n = g*16 + j;
        float nv = d_cnt2[n] > 0.f ? 1.f : 0.f;
        cnt += nv;
        s += nv * d_h3[n*F3 + t];
    }
    sf[t] = s / fmaxf(cnt, 1.f);
    __syncthreads();
    if (t < 10){
        float l = fcb[t];
        for (int i = 0; i < F3; i++) l += sf[i] * fcw[i*10 + t];
        slg[t] = l;
    }
    __syncthreads();
    if (t == 0){
        float mx = slg[0];
        for (int o = 1; o < 10; o++) mx = fmaxf(mx, slg[o]);
        float se = 0.f;
        for (int o = 0; o < 10; o++) se += expf(slg[o] - mx);
        float lse = logf(se) + mx;
        for (int o = 0; o < 10; o++) out[g*10 + o] = slg[o] - lse;
    }
}

// ---------------- launch ----------------
extern "C" void kernel_launch(void* const* d_in, const int* in_sizes, int n_in,
                              void* d_out, int out_size){
    const float* x    = (const float*)d_in[0];
    const float* pos  = (const float*)d_in[1];
    const int*   ei   = (const int*)  d_in[2];
    const float* W1   = (const float*)d_in[4];
    const float* r1   = (const float*)d_in[5];
    const float* b1   = (const float*)d_in[6];
    const float* W2   = (const float*)d_in[7];
    const float* r2p  = (const float*)d_in[8];
    const float* b2   = (const float*)d_in[9];
    const float* W3   = (const float*)d_in[10];
    const float* r3p  = (const float*)d_in[11];
    const float* b3   = (const float*)d_in[12];
    const float* fcw  = (const float*)d_in[13];
    const float* fcb  = (const float*)d_in[14];
    float* out = (float*)d_out;
    const int* row = ei;
    const int* col = ei + EE;

    k_init          <<<2048, 256>>>();
    k_m1            <<<1024, 256>>>(pos, row, col);
    k_scatter_remap1<<<EE/256, 256>>>(pos, x, row, col);
    k_node1pool1    <<<NN/8, 256>>>(x, W1, r1, b1, pos);
    k_fin1          <<<NC1*F1/256, 256>>>();
    k_pool2meta     <<<NC1/256, 256>>>();
    k_remap2        <<<512, 256>>>();
    k_m2            <<<512, 256>>>();
    k_fillBuckets   <<<1024, 256>>>();
    k_acc2          <<<NBKT, 32>>>();
    k_gemm2pool     <<<dim3(NC1/64, 1), 64>>>(W2, r2p, b2);
    k_fin2          <<<NC2*F2/256, 256>>>();
    k_m3            <<<128, 256>>>();
    k_fillB3        <<<128, 256>>>();
    k_bgemm3        <<<BG*KK, 256>>>();
    k_gemm3         <<<dim3(NC2/64, F3/64), 64>>>(W3, r3p, b3);
    k_readout       <<<BG, 128>>>(fcw, fcb, out);
}

// round 6
// speedup vs baseline: 1.5934x; 1.5934x over previous
#include <cuda_runtime.h>
#include <math.h>

// ---------------- problem constants ----------------
#define BG   256
#define NPG  256
#define NN   (BG*NPG)            // 65536 nodes
#define EE   (NN*16)             // 1048576 edges
#define KK   25
#define F1   32
#define F2   64
#define F3   128
#define NC1  (BG*64)             // 16384 pool-1 clusters
#define NC2  (BG*16)             // 4096  pool-2 clusters
#define BM1W (BG*4096/32)
#define BM2W (BG*256/32)

// ---------------- device scratch ----------------
__device__ float    d_m[4];
__device__ float    d_acc1[NN*32];          // 25 basis + slot25 = degree
__device__ float    d_x2[NC1*F1];
__device__ float    d_cnt1[NC1];
__device__ float    d_pos2[NC1*2];
__device__ unsigned d_bm1[BM1W];
__device__ unsigned d_bm2[BM2W];
__device__ int      d_bcnt2[NC1];
__device__ unsigned char d_bkt2[NC1*64];    // level-2: row-bucket of column ids (<=63)
__device__ int      d_bcnt3[NC2];
__device__ unsigned char d_bkt3[NC2*16];    // level-3: row-bucket of column ids (<=15)
__device__ float    d_acc2[(size_t)NC1*KK*F1];  // pre-divided by deg
__device__ float    d_x3[NC2*F2];
__device__ float    d_cnt2[NC2];
__device__ float    d_pos3[NC2*2];
__device__ float    d_acc3[(size_t)NC2*KK*F2];  // pre-divided by deg
__device__ float    d_h3[NC2*F3];

// ---------------- helpers ----------------
__device__ __forceinline__ float eluf(float v){ return v > 0.f ? v : expm1f(v); }

__device__ __forceinline__ void atomicMaxF(float* a, float v){
    if (v >= 0.f) atomicMax((int*)a, __float_as_int(v));
    else          atomicMin((unsigned int*)a, __float_as_uint(v));
}

__device__ __forceinline__ void warpMaxAtomic(float mx, float* dst){
    #pragma unroll
    for (int o = 16; o; o >>= 1) mx = fmaxf(mx, __shfl_xor_sync(0xffffffffu, mx, o));
    if ((threadIdx.x & 31) == 0) atomicMax((int*)dst, __float_as_int(mx));
}

__device__ __forceinline__ void spline_corners(float psx, float psy,
                                               int& ix, int& iy, float& fx, float& fy){
    float vx = psx * 4.f, vy = psy * 4.f;
    float fix = fminf(fmaxf(floorf(vx), 0.f), 3.f);
    float fiy = fminf(fmaxf(floorf(vy), 0.f), 3.f);
    fx = vx - fix; fy = vy - fiy;
    ix = (int)fix; iy = (int)fiy;
}

__device__ __forceinline__ int cell1(float px, float py){
    int cx = min(max((int)floorf(px * 0.25f), 0), 7);
    int cy = min(max((int)floorf(py * 0.25f), 0), 7);
    return cx * 8 + cy;
}
__device__ __forceinline__ int clu2_of(int j){
    float px = d_pos2[2*j], py = d_pos2[2*j+1];
    int cx = min(max((int)floorf(px * 0.125f), 0), 3);
    int cy = min(max((int)floorf(py * 0.125f), 0), 3);
    return (j >> 6) * 16 + cx * 4 + cy;
}

// f32x2 packed FMA helpers
__device__ __forceinline__ unsigned long long splat2(float x){
    unsigned long long r;
    asm("mov.b64 %0, {%1, %1};" : "=l"(r) : "f"(x));
    return r;
}
__device__ __forceinline__ void ffma2(unsigned long long& d,
                                      unsigned long long a, unsigned long long b){
    asm("fma.rn.f32x2 %0, %1, %2, %0;" : "+l"(d) : "l"(a), "l"(b));
}
__device__ __forceinline__ float f2lo(unsigned long long u){ return __uint_as_float((unsigned)u); }
__device__ __forceinline__ float f2hi(unsigned long long u){ return __uint_as_float((unsigned)(u>>32)); }

// ---------------- init (~11 MB) ----------------
__global__ void k_init(){
    long t = (long)blockIdx.x * blockDim.x + threadIdx.x;
    long S = (long)gridDim.x * blockDim.x;
    const float NEG = -3.4e38f;
    float4 z4 = make_float4(0.f,0.f,0.f,0.f);
    float4 n4 = make_float4(NEG,NEG,NEG,NEG);
    for (long i=t;i<(long)NN*32/4;i+=S) ((float4*)d_acc1)[i]=z4;
    for (long i=t;i<NC1*F1/4;     i+=S) ((float4*)d_x2)[i]=n4;
    for (long i=t;i<NC2*F2/4;     i+=S) ((float4*)d_x3)[i]=n4;
    for (long i=t;i<NC1;          i+=S){ d_cnt1[i]=0.f; d_bcnt2[i]=0; }
    for (long i=t;i<NC2;          i+=S){ d_cnt2[i]=0.f; d_bcnt3[i]=0; }
    for (long i=t;i<NC1*2;        i+=S) d_pos2[i]=0.f;
    for (long i=t;i<NC2*2;        i+=S) d_pos3[i]=0.f;
    for (long i=t;i<BM1W;         i+=S) d_bm1[i]=0u;
    for (long i=t;i<BM2W;         i+=S) d_bm2[i]=0u;
    if (t==0){ d_m[0]=d_m[1]=d_m[2]=0.f; }
}

// ---------------- layer 1 ----------------
__global__ void k_m1(const float* __restrict__ pos, const int* __restrict__ row,
                     const int* __restrict__ col){
    const float2* p2 = (const float2*)pos;
    float mx = 0.f;
    for (int e = blockIdx.x*blockDim.x + threadIdx.x; e < EE; e += gridDim.x*blockDim.x){
        float2 pr = p2[row[e]], pc = p2[col[e]];
        mx = fmaxf(mx, fmaxf(fabsf(pc.x - pr.x), fabsf(pc.y - pr.y)));
    }
    warpMaxAtomic(mx, &d_m[0]);
}

// fused: basis scatter (acc1 + degree) AND level-2 dedup append into row buckets
__global__ void k_scatter_remap1(const float* __restrict__ pos, const float* __restrict__ x,
                                 const int* __restrict__ row, const int* __restrict__ col){
    const float2* p2 = (const float2*)pos;
    int e = blockIdx.x*blockDim.x + threadIdx.x;   // grid sized exactly EE
    int r = row[e], c = col[e];
    float2 pr = p2[r], pc = p2[c];
    float inv = 1.f / (2.f * d_m[0] + 1e-12f);
    float psx = (pc.x - pr.x) * inv + 0.5f;
    float psy = (pc.y - pr.y) * inv + 0.5f;
    int ix, iy; float fx, fy;
    spline_corners(psx, psy, ix, iy, fx, fy);
    float xin = x[c];
    float wxs[2] = {1.f-fx, fx}, wys[2] = {1.f-fy, fy};
    #pragma unroll
    for (int sx=0; sx<2; sx++)
        #pragma unroll
        for (int sy=0; sy<2; sy++)
            atomicAdd(&d_acc1[r*32 + (ix+sx)*5 + (iy+sy)], wxs[sx]*wys[sy]*xin);
    atomicAdd(&d_acc1[r*32 + 25], 1.f);

    // level-2 dedup + bucket append
    int r2 = (r >> 8) * 64 + cell1(pr.x, pr.y);
    int c2 = (c >> 8) * 64 + cell1(pc.x, pc.y);
    if (r2 != c2){
        int key = ((r2 >> 6) << 12) | ((r2 & 63) << 6) | (c2 & 63);
        unsigned bit = 1u << (key & 31);
        unsigned old = atomicOr(&d_bm1[key >> 5], bit);
        if (!(old & bit)){
            int slot = atomicAdd(&d_bcnt2[r2], 1);
            d_bkt2[r2*64 + slot] = (unsigned char)(c2 & 63);
        }
    }
}

// fused node transform (layer 1) + grid pool 1 (no h1 buffer)
__global__ void k_node1pool1(const float* __restrict__ x, const float* __restrict__ W1,
                             const float* __restrict__ r1, const float* __restrict__ b1,
                             const float* __restrict__ pos){
    __shared__ float sW[KK*F1], sr[F1], sb[F1];
    for (int i = threadIdx.x; i < KK*F1; i += blockDim.x) sW[i] = W1[i];
    if (threadIdx.x < F1){ sr[threadIdx.x] = r1[threadIdx.x]; sb[threadIdx.x] = b1[threadIdx.x]; }
    __syncthreads();
    int n = blockIdx.x * 8 + (threadIdx.x >> 5);
    int o = threadIdx.x & 31;
    float s = 0.f;
    #pragma unroll
    for (int k4 = 0; k4 < 24; k4 += 4){
        float4 a = *(const float4*)&d_acc1[n*32 + k4];
        s += a.x * sW[(k4+0)*F1 + o];
        s += a.y * sW[(k4+1)*F1 + o];
        s += a.z * sW[(k4+2)*F1 + o];
        s += a.w * sW[(k4+3)*F1 + o];
    }
    s += d_acc1[n*32 + 24] * sW[24*F1 + o];
    float dg = fmaxf(d_acc1[n*32 + 25], 1.f);
    float2 p = ((const float2*)pos)[n];
    float h = eluf(s / dg + x[n] * sr[o] + sb[o]);
    int cl = (n >> 8) * 64 + cell1(p.x, p.y);
    atomicMaxF(&d_x2[cl*F1 + o], h);
    if (o == 0){
        atomicAdd(&d_cnt1[cl], 1.f);
        atomicAdd(&d_pos2[2*cl],   p.x);
        atomicAdd(&d_pos2[2*cl+1], p.y);
    }
}

__global__ void k_fin1(){
    int t = blockIdx.x*blockDim.x + threadIdx.x;
    if (t >= NC1*F1) return;
    int cl = t / F1, f = t % F1;
    float cnt = d_cnt1[cl];
    if (f < 2) d_pos2[2*cl + f] *= 1.f / fmaxf(cnt, 1.f);
    if (cnt <= 0.f) d_x2[t] = 0.f;
}

// pool-2 cluster meta (cnt2, pos3 sums)
__global__ void k_pool2meta(){
    int w = blockIdx.x*blockDim.x + threadIdx.x;
    if (w >= NC1) return;
    if (d_cnt1[w] <= 0.f) return;
    int cl = clu2_of(w);
    atomicAdd(&d_cnt2[cl], 1.f);
    atomicAdd(&d_pos3[2*cl],   d_pos2[2*w]);
    atomicAdd(&d_pos3[2*cl+1], d_pos2[2*w+1]);
}

__global__ void k_fin_pos3(){
    int cl = blockIdx.x*blockDim.x + threadIdx.x;
    if (cl >= NC2) return;
    float inv = 1.f / fmaxf(d_cnt2[cl], 1.f);
    d_pos3[2*cl]   *= inv;
    d_pos3[2*cl+1] *= inv;
}

// global pseudo-coord max over unique level-2 edges (bucket scan)
__global__ void k_m2(){
    int s = blockIdx.x*blockDim.x + threadIdx.x;   // NC1*64 slots
    float mx = 0.f;
    if (s < NC1*64){
        int r = s >> 6, slot = s & 63;
        if (slot < d_bcnt2[r]){
            int c = (r & ~63) | d_bkt2[r*64 + slot];
            float dx = d_pos2[2*c]   - d_pos2[2*r];
            float dy = d_pos2[2*c+1] - d_pos2[2*r+1];
            mx = fmaxf(fabsf(dx), fabsf(dy));
        }
    }
    warpMaxAtomic(mx, &d_m[1]);
}

// acc2[r,k,i] accumulated in SMEM; 8 warps/block, one warp per row; pre-divided by deg.
// Also fuses the level-3 dedup/append (lane 0).
__global__ void k_acc2(){
    __shared__ float acc_s[8*KK*F1];     // 25.6 KB [w][k][lane]
    __shared__ float xs[64*F1];          // 8 KB
    int b = blockIdx.x;                  // 2048 = BG*8
    int g = b >> 3, oct = b & 7;
    int t = threadIdx.x, w = t >> 5, lane = t & 31;
    float4 z4 = make_float4(0,0,0,0);
    for (int i = t; i < 8*KK*F1/4; i += 256) ((float4*)acc_s)[i] = z4;
    for (int i = t; i < 64*F1/4;   i += 256) ((float4*)xs)[i] = ((const float4*)(d_x2 + g*64*F1))[i];
    __syncthreads();

    int r = g*64 + oct*8 + w;           // global cluster row
    int cnt = d_bcnt2[r];
    float inv = 1.f / (2.f * d_m[1] + 1e-12f);
    float prx = d_pos2[2*r], pry = d_pos2[2*r+1];
    float* accr = &acc_s[w*KK*F1];
    int r3 = clu2_of(r);
    for (int e = 0; e < cnt; e++){
        int cl = d_bkt2[r*64 + e];
        int c = g*64 + cl;
        float psx = (d_pos2[2*c]   - prx) * inv + 0.5f;
        float psy = (d_pos2[2*c+1] - pry) * inv + 0.5f;
        int ix, iy; float fx, fy;
        spline_corners(psx, psy, ix, iy, fx, fy);
        float xv = xs[cl*F1 + lane];
        int kb = ix*5 + iy;
        float w00 = (1.f-fx)*(1.f-fy), w01 = (1.f-fx)*fy;
        float w10 = fx*(1.f-fy),       w11 = fx*fy;
        accr[(kb  )*F1 + lane] += w00 * xv;
        accr[(kb+1)*F1 + lane] += w01 * xv;
        accr[(kb+5)*F1 + lane] += w10 * xv;
        accr[(kb+6)*F1 + lane] += w11 * xv;
        if (lane == 0){
            int c3 = clu2_of(c);
            if (r3 != c3){
                int key = ((r3 >> 4) << 8) | ((r3 & 15) << 4) | (c3 & 15);
                unsigned bit = 1u << (key & 31);
                unsigned old = atomicOr(&d_bm2[key >> 5], bit);
                if (!(old & bit)){
                    int slot = atomicAdd(&d_bcnt3[r3], 1);
                    d_bkt3[r3*16 + slot] = (unsigned char)(c3 & 15);
                }
            }
        }
    }
    __syncwarp();
    float invd = 1.f / fmaxf((float)cnt, 1.f);
    size_t rowbase = (size_t)r * (KK*F1);
    #pragma unroll
    for (int k = 0; k < KK; k++)
        d_acc2[rowbase + k*F1 + lane] = accr[k*F1 + lane] * invd;
}

__global__ void k_m3(){
    int s = blockIdx.x*blockDim.x + threadIdx.x;   // NC2*16 slots
    float mx = 0.f;
    if (s < NC2*16){
        int r = s >> 4, slot = s & 15;
        if (slot < d_bcnt3[r]){
            int c = (r & ~15) | d_bkt3[r*16 + slot];
            float dx = d_pos3[2*c]   - d_pos3[2*r];
            float dy = d_pos3[2*c+1] - d_pos3[2*r+1];
            mx = fmaxf(fabsf(dx), fabsf(dy));
        }
    }
    warpMaxAtomic(mx, &d_m[2]);
}

// ---------------- 256-thread f32x2 GEMM: OUT = elu(A@W + XIN@ROOT + BIAS) ----------------
// A pre-divided by degree. TMH row-pairs x 4 cols per thread.
template<int BM, int TMH, int KDIM, int FIN, int NOUT, bool POOL>
__device__ __forceinline__ void gemm_body(
    const float* __restrict__ A, const float* __restrict__ W,
    const float* __restrict__ XIN, const float* __restrict__ ROOT,
    const float* __restrict__ BIAS, float* __restrict__ OUT)
{
    const int BK = 16, TM = 2*TMH;
    __shared__ float As[BK][BM + 4];
    __shared__ float Bs[BK][64];
    int bm = blockIdx.x * BM;
    int bn = blockIdx.y * 64;
    int t  = threadIdx.x;            // 256
    int tx = t & 15, ty = t >> 4;
    unsigned long long acc[TMH][4];
    #pragma unroll
    for (int p=0;p<TMH;p++)
        #pragma unroll
        for (int j=0;j<4;j++) acc[p][j]=0ull;

    const int KTOT = KDIM + FIN;
    for (int kk = 0; kk < KTOT; kk += BK){
        bool ext = (kk >= KDIM);
        const float* srcA = ext ? XIN : A;
        const float* srcB = ext ? ROOT : W;
        int ld   = ext ? FIN : KDIM;
        int kofs = ext ? (kk - KDIM) : kk;
        #pragma unroll
        for (int w = 0; w < BM/64; w++){
            int idx = (t + w*256) * 4;
            int m = idx >> 4, k4 = idx & 15;
            float4 v = *(const float4*)&srcA[(size_t)(bm+m)*ld + kofs + k4];
            As[k4+0][m]=v.x; As[k4+1][m]=v.y; As[k4+2][m]=v.z; As[k4+3][m]=v.w;
        }
        {
            int k = t >> 4, n4 = (t & 15) * 4;
            *(float4*)&Bs[k][n4] = *(const float4*)&srcB[(size_t)(kofs+k)*NOUT + bn + n4];
        }
        __syncthreads();
        #pragma unroll
        for (int kb = 0; kb < BK; kb++){
            unsigned long long a[TMH];
            #pragma unroll
            for (int p=0;p<TMH;p++)
                a[p] = *(const unsigned long long*)&As[kb][ty*TM + 2*p];
            float4 b4 = *(const float4*)&Bs[kb][tx*4];
            unsigned long long b0=splat2(b4.x), b1=splat2(b4.y),
                               b2=splat2(b4.z), b3=splat2(b4.w);
            #pragma unroll
            for (int p=0;p<TMH;p++){
                ffma2(acc[p][0], a[p], b0);
                ffma2(acc[p][1], a[p], b1);
                ffma2(acc[p][2], a[p], b2);
                ffma2(acc[p][3], a[p], b3);
            }
        }
        __syncthreads();
    }
    #pragma unroll
    for (int p = 0; p < TMH; p++){
        int m0 = bm + ty*TM + 2*p;
        int ob = bn + tx*4;
        if (POOL){
            #pragma unroll
            for (int half = 0; half < 2; half++){
                int m = m0 + half;
                if (d_cnt1[m] <= 0.f) continue;
                int cl = clu2_of(m);
                #pragma unroll
                for (int j = 0; j < 4; j++){
                    float v = half ? f2hi(acc[p][j]) : f2lo(acc[p][j]);
                    atomicMaxF(&d_x3[cl*F2 + ob + j], eluf(v + BIAS[ob + j]));
                }
            }
        } else {
            float b0 = BIAS[ob], b1 = BIAS[ob+1], b2 = BIAS[ob+2], b3 = BIAS[ob+3];
            float4 o0 = make_float4(eluf(f2lo(acc[p][0])+b0), eluf(f2lo(acc[p][1])+b1),
                                    eluf(f2lo(acc[p][2])+b2), eluf(f2lo(acc[p][3])+b3));
            float4 o1 = make_float4(eluf(f2hi(acc[p][0])+b0), eluf(f2hi(acc[p][1])+b1),
                                    eluf(f2hi(acc[p][2])+b2), eluf(f2hi(acc[p][3])+b3));
            *(float4*)&OUT[(size_t)m0*NOUT + ob]     = o0;
            *(float4*)&OUT[(size_t)(m0+1)*NOUT + ob] = o1;
        }
    }
}

__global__ void k_gemm2pool(const float* __restrict__ W, const float* __restrict__ ROOT,
                            const float* __restrict__ BIAS){
    gemm_body<64, 2, KK*F1, F1, F2, true>(d_acc2, W, d_x2, ROOT, BIAS, d_x3);
}
__global__ void k_gemm3(const float* __restrict__ W, const float* __restrict__ ROOT,
                        const float* __restrict__ BIAS){
    gemm_body<64, 2, KK*F2, F2, F3, false>(d_acc3, W, d_x3, ROOT, BIAS, d_h3);
}

__global__ void k_fin_x3(){
    int t = blockIdx.x*blockDim.x + threadIdx.x;
    if (t >= NC2*F2) return;
    if (d_cnt2[t / F2] <= 0.f) d_x3[t] = 0.f;
}

// acc3 in SMEM; 8 warps/block, warp per row; pre-divided by deg
__global__ void k_acc3(){
    __shared__ float acc_s[8*KK*F2];     // 51.2 KB
    __shared__ float xs[16*F2];          // 4 KB
    int b = blockIdx.x;                  // 512 = BG*2
    int g = b >> 1, half = b & 1;
    int t = threadIdx.x, w = t >> 5, lane = t & 31;
    float4 z4 = make_float4(0,0,0,0);
    for (int i = t; i < 8*KK*F2/4; i += 256) ((float4*)acc_s)[i] = z4;
    for (int i = t; i < 16*F2/4;   i += 256) ((float4*)xs)[i] = ((const float4*)(d_x3 + g*16*F2))[i];
    __syncthreads();

    int r = g*16 + half*8 + w;
    int cnt = d_bcnt3[r];
    float inv = 1.f / (2.f * d_m[2] + 1e-12f);
    float prx = d_pos3[2*r], pry = d_pos3[2*r+1];
    float* accr = &acc_s[w*KK*F2];
    for (int e = 0; e < cnt; e++){
        int cl = d_bkt3[r*16 + e];
        int c = g*16 + cl;
        float psx = (d_pos3[2*c]   - prx) * inv + 0.5f;
        float psy = (d_pos3[2*c+1] - pry) * inv + 0.5f;
        int ix, iy; float fx, fy;
        spline_corners(psx, psy, ix, iy, fx, fy);
        float xv0 = xs[cl*F2 + lane];
        float xv1 = xs[cl*F2 + lane + 32];
        int kb = ix*5 + iy;
        float w00 = (1.f-fx)*(1.f-fy), w01 = (1.f-fx)*fy;
        float w10 = fx*(1.f-fy),       w11 = fx*fy;
        accr[(kb  )*F2 + lane]      += w00 * xv0;
        accr[(kb  )*F2 + lane + 32] += w00 * xv1;
        accr[(kb+1)*F2 + lane]      += w01 * xv0;
        accr[(kb+1)*F2 + lane + 32] += w01 * xv1;
        accr[(kb+5)*F2 + lane]      += w10 * xv0;
        accr[(kb+5)*F2 + lane + 32] += w10 * xv1;
        accr[(kb+6)*F2 + lane]      += w11 * xv0;
        accr[(kb+6)*F2 + lane + 32] += w11 * xv1;
    }
    __syncwarp();
    float invd = 1.f / fmaxf((float)cnt, 1.f);
    size_t rowbase = (size_t)r * (KK*F2);
    #pragma unroll
    for (int k = 0; k < KK; k++){
        d_acc3[rowbase + k*F2 + lane]      = accr[k*F2 + lane]      * invd;
        d_acc3[rowbase + k*F2 + lane + 32] = accr[k*F2 + lane + 32] * invd;
    }
}

// ---------------- readout ----------------
__global__ void k_readout(const float* __restrict__ fcw, const float* __restrict__ fcb,
                          float* __restrict__ out){
    int g = blockIdx.x, t = threadIdx.x;     // 128 threads
    __shared__ float sf[F3];
    __shared__ float slg[10];
    float s = 0.f, cnt = 0.f;
    for (int j = 0; j < 16; j++){
        int n = g*16 + j;
        float nv = d_cnt2[n] > 0.f ? 1.f : 0.f;
        cnt += nv;
        s += nv * d_h3[n*F3 + t];
    }
    sf[t] = s / fmaxf(cnt, 1.f);
    __syncthreads();
    if (t < 10){
        float l = fcb[t];
        for (int i = 0; i < F3; i++) l += sf[i] * fcw[i*10 + t];
        slg[t] = l;
    }
    __syncthreads();
    if (t == 0){
        float mx = slg[0];
        for (int o = 1; o < 10; o++) mx = fmaxf(mx, slg[o]);
        float se = 0.f;
        for (int o = 0; o < 10; o++) se += expf(slg[o] - mx);
        float lse = logf(se) + mx;
        for (int o = 0; o < 10; o++) out[g*10 + o] = slg[o] - lse;
    }
}

// ---------------- launch ----------------
extern "C" void kernel_launch(void* const* d_in, const int* in_sizes, int n_in,
                              void* d_out, int out_size){
    const float* x    = (const float*)d_in[0];
    const float* pos  = (const float*)d_in[1];
    const int*   ei   = (const int*)  d_in[2];
    const float* W1   = (const float*)d_in[4];
    const float* r1   = (const float*)d_in[5];
    const float* b1   = (const float*)d_in[6];
    const float* W2   = (const float*)d_in[7];
    const float* r2p  = (const float*)d_in[8];
    const float* b2   = (const float*)d_in[9];
    const float* W3   = (const float*)d_in[10];
    const float* r3p  = (const float*)d_in[11];
    const float* b3   = (const float*)d_in[12];
    const float* fcw  = (const float*)d_in[13];
    const float* fcb  = (const float*)d_in[14];
    float* out = (float*)d_out;
    const int* row = ei;
    const int* col = ei + EE;

    k_init          <<<1024, 256>>>();
    k_m1            <<<1024, 256>>>(pos, row, col);
    k_scatter_remap1<<<EE/256, 256>>>(pos, x, row, col);
    k_node1pool1    <<<NN/8, 256>>>(x, W1, r1, b1, pos);
    k_fin1          <<<NC1*F1/256, 256>>>();
    k_pool2meta     <<<NC1/256, 256>>>();
    k_fin_pos3      <<<NC2/256, 256>>>();
    k_m2            <<<NC1*64/256, 256>>>();
    k_acc2          <<<BG*8, 256>>>();
    k_m3            <<<NC2*16/256, 256>>>();
    k_gemm2pool     <<<dim3(NC1/64, 1), 256>>>(W2, r2p, b2);
    k_fin_x3        <<<NC2*F2/256, 256>>>();
    k_acc3          <<<BG*2, 256>>>();
    k_gemm3         <<<dim3(NC2/64, F3/64), 256>>>(W3, r3p, b3);
    k_readout       <<<BG, 128>>>(fcw, fcb, out);
}

// round 7
// speedup vs baseline: 2.1720x; 1.3631x over previous
#include <cuda_runtime.h>
#include <math.h>

// ---------------- problem constants ----------------
#define BG   256
#define NPG  256
#define NN   (BG*NPG)            // 65536 nodes
#define EE   (NN*16)             // 1048576 edges
#define KK   25
#define F1   32
#define F2   64
#define F3   128
#define NC1  (BG*64)             // 16384 pool-1 clusters
#define NC2  (BG*16)             // 4096  pool-2 clusters
#define NBCAP 64                 // max in-edges per node (avg 16; Binom tail ~0)

// ---------------- device scratch ----------------
__device__ float    d_m[4];
__device__ int      d_ncnt1[NN];
__device__ unsigned char d_nbuf[(size_t)NN*NBCAP];   // 4MB: per-node source bytes
__device__ float    d_x2[NC1*F1];
__device__ float    d_cnt1[NC1];
__device__ float    d_pos2[NC1*2];
__device__ int      d_bcnt2[NC1];
__device__ unsigned char d_bkt2[NC1*64];
__device__ int      d_bcnt3[NC2];
__device__ unsigned char d_bkt3[NC2*16];
__device__ float    d_acc2[(size_t)NC1*KK*F1];  // pre-divided by deg
__device__ float    d_x3[NC2*F2];
__device__ float    d_cnt2[NC2];
__device__ float    d_pos3[NC2*2];
__device__ float    d_acc3[(size_t)NC2*KK*F2];  // pre-divided by deg
__device__ float    d_h3[NC2*F3];

// ---------------- helpers ----------------
__device__ __forceinline__ float eluf(float v){ return v > 0.f ? v : expm1f(v); }

__device__ __forceinline__ void atomicMaxF(float* a, float v){
    if (v >= 0.f) atomicMax((int*)a, __float_as_int(v));
    else          atomicMin((unsigned int*)a, __float_as_uint(v));
}

__device__ __forceinline__ void warpMaxAtomic(float mx, float* dst){
    #pragma unroll
    for (int o = 16; o; o >>= 1) mx = fmaxf(mx, __shfl_xor_sync(0xffffffffu, mx, o));
    if ((threadIdx.x & 31) == 0) atomicMax((int*)dst, __float_as_int(mx));
}

__device__ __forceinline__ void spline_corners(float psx, float psy,
                                               int& ix, int& iy, float& fx, float& fy){
    float vx = psx * 4.f, vy = psy * 4.f;
    float fix = fminf(fmaxf(floorf(vx), 0.f), 3.f);
    float fiy = fminf(fmaxf(floorf(vy), 0.f), 3.f);
    fx = vx - fix; fy = vy - fiy;
    ix = (int)fix; iy = (int)fiy;
}

__device__ __forceinline__ int cell1(float px, float py){
    int cx = min(max((int)floorf(px * 0.25f), 0), 7);
    int cy = min(max((int)floorf(py * 0.25f), 0), 7);
    return cx * 8 + cy;
}
__device__ __forceinline__ int clu2_of(int j){
    float px = d_pos2[2*j], py = d_pos2[2*j+1];
    int cx = min(max((int)floorf(px * 0.125f), 0), 3);
    int cy = min(max((int)floorf(py * 0.125f), 0), 3);
    return (j >> 6) * 16 + cx * 4 + cy;
}

// f32x2 packed FMA helpers
__device__ __forceinline__ unsigned long long splat2(float x){
    unsigned long long r;
    asm("mov.b64 %0, {%1, %1};" : "=l"(r) : "f"(x));
    return r;
}
__device__ __forceinline__ void ffma2(unsigned long long& d,
                                      unsigned long long a, unsigned long long b){
    asm("fma.rn.f32x2 %0, %1, %2, %0;" : "+l"(d) : "l"(a), "l"(b));
}
__device__ __forceinline__ float f2lo(unsigned long long u){ return __uint_as_float((unsigned)u); }
__device__ __forceinline__ float f2hi(unsigned long long u){ return __uint_as_float((unsigned)(u>>32)); }

// ---------------- init (1.3 MB) ----------------
__global__ void k_init(){
    int t = blockIdx.x*blockDim.x + threadIdx.x;     // 65536
    const float NEG = -3.4e38f;
    ((float4*)d_x3)[t] = make_float4(NEG,NEG,NEG,NEG);   // NC2*F2/4 = 65536
    d_ncnt1[t] = 0;
    if (t < 4) d_m[t] = 0.f;
}

// bucket edges by target node (source fits in one byte: same graph)
__global__ void k_nbucket(const int* __restrict__ row, const int* __restrict__ col){
    int e = blockIdx.x*blockDim.x + threadIdx.x;
    int n = row[e], c = col[e];
    int slot = atomicAdd(&d_ncnt1[n], 1);
    if (slot < NBCAP) d_nbuf[(size_t)n*NBCAP + slot] = (unsigned char)(c & 255);
}

// global pseudo max (level 1) from compact per-node edges; block per graph
__global__ void k_m1g(const float* __restrict__ pos){
    __shared__ float2 ps[NPG];
    int g = blockIdx.x, t = threadIdx.x;
    ps[t] = ((const float2*)pos)[g*NPG + t];
    __syncthreads();
    int gn = g*NPG + t;
    int cnt = min(d_ncnt1[gn], NBCAP);
    const unsigned char* nb = d_nbuf + (size_t)gn*NBCAP;
    float2 mp = ps[t];
    float mx = 0.f;
    for (int e = 0; e < cnt; e++){
        float2 pc = ps[nb[e]];
        mx = fmaxf(mx, fmaxf(fabsf(pc.x - mp.x), fabsf(pc.y - mp.y)));
    }
    warpMaxAtomic(mx, &d_m[0]);
}

// ---------------- mega-kernel: layer1 conv+pool + level2/3 graph build ----------------
__global__ void __launch_bounds__(256) k_graph1(
        const float* __restrict__ x, const float* __restrict__ pos,
        const float* __restrict__ W1, const float* __restrict__ r1,
        const float* __restrict__ b1){
    __shared__ float  acc_s[NPG*26];       // 26.6KB  [node][k] basis accum (non-atomic, thread-owned)
    __shared__ float  x2_s[64*F1];         // 8KB
    __shared__ unsigned char bkt_s[64*64]; // 4KB
    __shared__ float  W1s[KK*F1];          // 3.2KB
    __shared__ float2 ps[NPG];             // 2KB
    __shared__ float  xs_s[NPG];           // 1KB
    __shared__ unsigned char cell_s[NPG];
    __shared__ unsigned bm_s[128];
    __shared__ int    bcnt_s[64];
    __shared__ float  cnt1_s[64];
    __shared__ float  pos2_s[64*2];
    __shared__ unsigned char cell2_s[64];
    __shared__ unsigned bm3_s[8];
    __shared__ int    bcnt3_s[16];
    __shared__ unsigned char bkt3_s[16*16];
    __shared__ float  cnt2_s[16];
    __shared__ float  pos3_s[16*2];
    __shared__ float  r1s[F1], b1s[F1];

    int g = blockIdx.x, t = threadIdx.x;
    int gn = g*NPG + t;

    // ---- P1: loads + zeroing ----
    float2 myp = ((const float2*)pos)[gn];
    ps[t] = myp;
    xs_s[t] = x[gn];
    for (int i = t; i < KK*F1; i += 256) W1s[i] = W1[i];
    if (t < F1){ r1s[t] = r1[t]; b1s[t] = b1[t]; }
    cell_s[t] = (unsigned char)cell1(myp.x, myp.y);
    #pragma unroll
    for (int k = 0; k < 26; k++) acc_s[t*26 + k] = 0.f;
    {
        const float NEG = -3.4e38f;
        for (int i = t; i < 64*F1; i += 256) x2_s[i] = NEG;
    }
    if (t < 128) bm_s[t] = 0u;
    if (t < 64){ bcnt_s[t] = 0; cnt1_s[t] = 0.f; pos2_s[2*t] = 0.f; pos2_s[2*t+1] = 0.f; }
    if (t < 16){ bcnt3_s[t] = 0; cnt2_s[t] = 0.f; pos3_s[2*t] = 0.f; pos3_s[2*t+1] = 0.f; }
    if (t < 8) bm3_s[t] = 0u;
    __syncthreads();

    // ---- P2: per-node edge accumulation + level-2 dedup ----
    int rawcnt = d_ncnt1[gn];
    int cnt = min(rawcnt, NBCAP);
    const unsigned char* nb = d_nbuf + (size_t)gn*NBCAP;
    float inv1 = 1.f / (2.f * d_m[0] + 1e-12f);
    float* ar = &acc_s[t*26];
    int r2cell = cell_s[t];
    for (int e = 0; e < cnt; e++){
        int c = nb[e];
        float2 pc = ps[c];
        float psx = (pc.x - myp.x) * inv1 + 0.5f;
        float psy = (pc.y - myp.y) * inv1 + 0.5f;
        int ix, iy; float fx, fy;
        spline_corners(psx, psy, ix, iy, fx, fy);
        float xin = xs_s[c];
        int kb = ix*5 + iy;
        float w00 = (1.f-fx)*(1.f-fy), w01 = (1.f-fx)*fy;
        float w10 = fx*(1.f-fy),       w11 = fx*fy;
        ar[kb  ] += w00 * xin;
        ar[kb+1] += w01 * xin;
        ar[kb+5] += w10 * xin;
        ar[kb+6] += w11 * xin;
        int c2 = cell_s[c];
        if (r2cell != c2){
            int key = r2cell*64 + c2;
            unsigned bit = 1u << (key & 31);
            unsigned old = atomicOr(&bm_s[key >> 5], bit);
            if (!(old & bit)){
                int sl = atomicAdd(&bcnt_s[r2cell], 1);
                bkt_s[r2cell*64 + sl] = (unsigned char)c2;
            }
        }
    }
    __syncthreads();

    // ---- P3: node transform (registers) + pool-1 into SMEM ----
    {
        float invd = 1.f / fmaxf((float)rawcnt, 1.f);
        float xn = xs_s[t];
        float h[F1];
        #pragma unroll
        for (int o = 0; o < F1; o++) h[o] = b1s[o] + xn * r1s[o];
        #pragma unroll
        for (int k = 0; k < KK; k++){
            float a = ar[k] * invd;
            #pragma unroll
            for (int o = 0; o < F1; o++) h[o] += a * W1s[k*F1 + o];
        }
        int cl = r2cell;
        atomicAdd(&cnt1_s[cl], 1.f);
        atomicAdd(&pos2_s[2*cl],   myp.x);
        atomicAdd(&pos2_s[2*cl+1], myp.y);
        #pragma unroll
        for (int o = 0; o < F1; o++)
            atomicMaxF(&x2_s[cl*F1 + o], eluf(h[o]));
    }
    __syncthreads();

    // ---- P4: finalize clusters ----
    if (t < 64){
        float c = cnt1_s[t];
        float invc = 1.f / fmaxf(c, 1.f);
        float px = pos2_s[2*t] * invc, py = pos2_s[2*t+1] * invc;
        pos2_s[2*t] = px; pos2_s[2*t+1] = py;
        int cx = min(max((int)floorf(px * 0.125f), 0), 3);
        int cy = min(max((int)floorf(py * 0.125f), 0), 3);
        cell2_s[t] = (unsigned char)(cx*4 + cy);
        d_cnt1[g*64 + t] = c;
        d_pos2[(g*64 + t)*2]     = px;
        d_pos2[(g*64 + t)*2 + 1] = py;
        d_bcnt2[g*64 + t] = bcnt_s[t];
    }
    __syncthreads();

    // ---- P5: write x2 (zero empty clusters) + pool-2 meta ----
    for (int i = t; i < 64*F1; i += 256){
        int cl = i >> 5;
        d_x2[g*64*F1 + i] = (cnt1_s[cl] > 0.f) ? x2_s[i] : 0.f;
    }
    if (t < 64 && cnt1_s[t] > 0.f){
        int c2 = cell2_s[t];
        atomicAdd(&cnt2_s[c2], 1.f);
        atomicAdd(&pos3_s[2*c2],   pos2_s[2*t]);
        atomicAdd(&pos3_s[2*c2+1], pos2_s[2*t+1]);
    }
    __syncthreads();

    // ---- P6: finalize pool-2 positions ----
    if (t < 16){
        float c = cnt2_s[t];
        float invc = 1.f / fmaxf(c, 1.f);
        pos3_s[2*t]   *= invc;
        pos3_s[2*t+1] *= invc;
        d_cnt2[g*16 + t] = c;
        d_pos3[(g*16 + t)*2]     = pos3_s[2*t];
        d_pos3[(g*16 + t)*2 + 1] = pos3_s[2*t+1];
    }
    __syncthreads();

    // ---- P7: m2 partial + build level-3 buckets; write level-2 buckets ----
    {
        float mx = 0.f;
        for (int i = t; i < 64*64; i += 256){
            int r = i >> 6, s = i & 63;
            if (s < bcnt_s[r]){
                int c = bkt_s[i];
                float dx = pos2_s[2*c]   - pos2_s[2*r];
                float dy = pos2_s[2*c+1] - pos2_s[2*r+1];
                mx = fmaxf(mx, fmaxf(fabsf(dx), fabsf(dy)));
                int r3 = cell2_s[r], c3 = cell2_s[c];
                if (r3 != c3){
                    int key = r3*16 + c3;
                    unsigned bit = 1u << (key & 31);
                    unsigned old = atomicOr(&bm3_s[key >> 5], bit);
                    if (!(old & bit)){
                        int sl = atomicAdd(&bcnt3_s[r3], 1);
                        bkt3_s[r3*16 + sl] = (unsigned char)c3;
                    }
                }
            }
        }
        warpMaxAtomic(mx, &d_m[1]);
    }
    ((uint4*)(d_bkt2 + (size_t)g*4096))[t] = ((uint4*)bkt_s)[t];
    __syncthreads();

    // ---- P8: m3 partial; write level-3 buckets ----
    {
        float mx = 0.f;
        int r = t >> 4, s = t & 15;
        if (s < bcnt3_s[r]){
            int c = bkt3_s[t];
            float dx = pos3_s[2*c]   - pos3_s[2*r];
            float dy = pos3_s[2*c+1] - pos3_s[2*r+1];
            mx = fmaxf(fabsf(dx), fabsf(dy));
        }
        warpMaxAtomic(mx, &d_m[2]);
    }
    if (t < 16){
        d_bcnt3[g*16 + t] = bcnt3_s[t];
        ((uint4*)(d_bkt3 + g*256))[t] = ((uint4*)bkt3_s)[t];
    }
}

// acc2[r,k,i] in SMEM; 8 warps/block, one warp per row; pre-divided by deg
__global__ void k_acc2(){
    __shared__ float acc_s[8*KK*F1];     // 25.6 KB
    __shared__ float xs[64*F1];          // 8 KB
    int b = blockIdx.x;                  // 2048 = BG*8
    int g = b >> 3, oct = b & 7;
    int t = threadIdx.x, w = t >> 5, lane = t & 31;
    float4 z4 = make_float4(0,0,0,0);
    for (int i = t; i < 8*KK*F1/4; i += 256) ((float4*)acc_s)[i] = z4;
    for (int i = t; i < 64*F1/4;   i += 256) ((float4*)xs)[i] = ((const float4*)(d_x2 + g*64*F1))[i];
    __syncthreads();

    int r = g*64 + oct*8 + w;
    int cnt = d_bcnt2[r];
    float inv = 1.f / (2.f * d_m[1] + 1e-12f);
    float prx = d_pos2[2*r], pry = d_pos2[2*r+1];
    float* accr = &acc_s[w*KK*F1];
    for (int e = 0; e < cnt; e++){
        int cl = d_bkt2[r*64 + e];
        int c = g*64 + cl;
        float psx = (d_pos2[2*c]   - prx) * inv + 0.5f;
        float psy = (d_pos2[2*c+1] - pry) * inv + 0.5f;
        int ix, iy; float fx, fy;
        spline_corners(psx, psy, ix, iy, fx, fy);
        float xv = xs[cl*F1 + lane];
        int kb = ix*5 + iy;
        float w00 = (1.f-fx)*(1.f-fy), w01 = (1.f-fx)*fy;
        float w10 = fx*(1.f-fy),       w11 = fx*fy;
        accr[(kb  )*F1 + lane] += w00 * xv;
        accr[(kb+1)*F1 + lane] += w01 * xv;
        accr[(kb+5)*F1 + lane] += w10 * xv;
        accr[(kb+6)*F1 + lane] += w11 * xv;
    }
    __syncwarp();
    float invd = 1.f / fmaxf((float)cnt, 1.f);
    size_t rowbase = (size_t)r * (KK*F1);
    #pragma unroll
    for (int k = 0; k < KK; k++)
        d_acc2[rowbase + k*F1 + lane] = accr[k*F1 + lane] * invd;
}

// ---------------- 256-thread f32x2 GEMM: OUT = elu(A@W + XIN@ROOT + BIAS) ----------------
template<int BM, int TMH, int KDIM, int FIN, int NOUT, bool POOL>
__device__ __forceinline__ void gemm_body(
    const float* __restrict__ A, const float* __restrict__ W,
    const float* __restrict__ XIN, const float* __restrict__ ROOT,
    const float* __restrict__ BIAS, float* __restrict__ OUT)
{
    const int BK = 16, TM = 2*TMH;
    __shared__ float As[BK][BM + 4];
    __shared__ float Bs[BK][64];
    int bm = blockIdx.x * BM;
    int bn = blockIdx.y * 64;
    int t  = threadIdx.x;            // 256
    int tx = t & 15, ty = t >> 4;
    unsigned long long acc[TMH][4];
    #pragma unroll
    for (int p=0;p<TMH;p++)
        #pragma unroll
        for (int j=0;j<4;j++) acc[p][j]=0ull;

    const int KTOT = KDIM + FIN;
    for (int kk = 0; kk < KTOT; kk += BK){
        bool ext = (kk >= KDIM);
        const float* srcA = ext ? XIN : A;
        const float* srcB = ext ? ROOT : W;
        int ld   = ext ? FIN : KDIM;
        int kofs = ext ? (kk - KDIM) : kk;
        #pragma unroll
        for (int w = 0; w < BM/64; w++){
            int idx = (t + w*256) * 4;
            int m = idx >> 4, k4 = idx & 15;
            float4 v = *(const float4*)&srcA[(size_t)(bm+m)*ld + kofs + k4];
            As[k4+0][m]=v.x; As[k4+1][m]=v.y; As[k4+2][m]=v.z; As[k4+3][m]=v.w;
        }
        {
            int k = t >> 4, n4 = (t & 15) * 4;
            *(float4*)&Bs[k][n4] = *(const float4*)&srcB[(size_t)(kofs+k)*NOUT + bn + n4];
        }
        __syncthreads();
        #pragma unroll
        for (int kb = 0; kb < BK; kb++){
            unsigned long long a[TMH];
            #pragma unroll
            for (int p=0;p<TMH;p++)
                a[p] = *(const unsigned long long*)&As[kb][ty*TM + 2*p];
            float4 b4 = *(const float4*)&Bs[kb][tx*4];
            unsigned long long b0=splat2(b4.x), b1=splat2(b4.y),
                               b2=splat2(b4.z), b3=splat2(b4.w);
            #pragma unroll
            for (int p=0;p<TMH;p++){
                ffma2(acc[p][0], a[p], b0);
                ffma2(acc[p][1], a[p], b1);
                ffma2(acc[p][2], a[p], b2);
                ffma2(acc[p][3], a[p], b3);
            }
        }
        __syncthreads();
    }
    #pragma unroll
    for (int p = 0; p < TMH; p++){
        int m0 = bm + ty*TM + 2*p;
        int ob = bn + tx*4;
        if (POOL){
            #pragma unroll
            for (int half = 0; half < 2; half++){
                int m = m0 + half;
                if (d_cnt1[m] <= 0.f) continue;
                int cl = clu2_of(m);
                #pragma unroll
                for (int j = 0; j < 4; j++){
                    float v = half ? f2hi(acc[p][j]) : f2lo(acc[p][j]);
                    atomicMaxF(&d_x3[cl*F2 + ob + j], eluf(v + BIAS[ob + j]));
                }
            }
        } else {
            float b0 = BIAS[ob], b1 = BIAS[ob+1], b2 = BIAS[ob+2], b3 = BIAS[ob+3];
            float4 o0 = make_float4(eluf(f2lo(acc[p][0])+b0), eluf(f2lo(acc[p][1])+b1),
                                    eluf(f2lo(acc[p][2])+b2), eluf(f2lo(acc[p][3])+b3));
            float4 o1 = make_float4(eluf(f2hi(acc[p][0])+b0), eluf(f2hi(acc[p][1])+b1),
                                    eluf(f2hi(acc[p][2])+b2), eluf(f2hi(acc[p][3])+b3));
            *(float4*)&OUT[(size_t)m0*NOUT + ob]     = o0;
            *(float4*)&OUT[(size_t)(m0+1)*NOUT + ob] = o1;
        }
    }
}

__global__ void k_gemm2pool(const float* __restrict__ W, const float* __restrict__ ROOT,
                            const float* __restrict__ BIAS){
    gemm_body<64, 2, KK*F1, F1, F2, true>(d_acc2, W, d_x2, ROOT, BIAS, d_x3);
}
__global__ void k_gemm3(const float* __restrict__ W, const float* __restrict__ ROOT,
                        const float* __restrict__ BIAS){
    gemm_body<64, 2, KK*F2, F2, F3, false>(d_acc3, W, d_x3, ROOT, BIAS, d_h3);
}

__global__ void k_fin_x3(){
    int t = blockIdx.x*blockDim.x + threadIdx.x;
    if (t >= NC2*F2) return;
    if (d_cnt2[t / F2] <= 0.f) d_x3[t] = 0.f;
}

// acc3 in SMEM; 8 warps/block, warp per row; pre-divided by deg
__global__ void k_acc3(){
    __shared__ float acc_s[8*KK*F2];     // 51.2 KB
    __shared__ float xs[16*F2];          // 4 KB
    int b = blockIdx.x;                  // 512 = BG*2
    int g = b >> 1, half = b & 1;
    int t = threadIdx.x, w = t >> 5, lane = t & 31;
    float4 z4 = make_float4(0,0,0,0);
    for (int i = t; i < 8*KK*F2/4; i += 256) ((float4*)acc_s)[i] = z4;
    for (int i = t; i < 16*F2/4;   i += 256) ((float4*)xs)[i] = ((const float4*)(d_x3 + g*16*F2))[i];
    __syncthreads();

    int r = g*16 + half*8 + w;
    int cnt = d_bcnt3[r];
    float inv = 1.f / (2.f * d_m[2] + 1e-12f);
    float prx = d_pos3[2*r], pry = d_pos3[2*r+1];
    float* accr = &acc_s[w*KK*F2];
    for (int e = 0; e < cnt; e++){
        int cl = d_bkt3[r*16 + e];
        int c = g*16 + cl;
        float psx = (d_pos3[2*c]   - prx) * inv + 0.5f;
        float psy = (d_pos3[2*c+1] - pry) * inv + 0.5f;
        int ix, iy; float fx, fy;
        spline_corners(psx, psy, ix, iy, fx, fy);
        float xv0 = xs[cl*F2 + lane];
        float xv1 = xs[cl*F2 + lane + 32];
        int kb = ix*5 + iy;
        float w00 = (1.f-fx)*(1.f-fy), w01 = (1.f-fx)*fy;
        float w10 = fx*(1.f-fy),       w11 = fx*fy;
        accr[(kb  )*F2 + lane]      += w00 * xv0;
        accr[(kb  )*F2 + lane + 32] += w00 * xv1;
        accr[(kb+1)*F2 + lane]      += w01 * xv0;
        accr[(kb+1)*F2 + lane + 32] += w01 * xv1;
        accr[(kb+5)*F2 + lane]      += w10 * xv0;
        accr[(kb+5)*F2 + lane + 32] += w10 * xv1;
        accr[(kb+6)*F2 + lane]      += w11 * xv0;
        accr[(kb+6)*F2 + lane + 32] += w11 * xv1;
    }
    __syncwarp();
    float invd = 1.f / fmaxf((float)cnt, 1.f);
    size_t rowbase = (size_t)r * (KK*F2);
    #pragma unroll
    for (int k = 0; k < KK; k++){
        d_acc3[rowbase + k*F2 + lane]      = accr[k*F2 + lane]      * invd;
        d_acc3[rowbase + k*F2 + lane + 32] = accr[k*F2 + lane + 32] * invd;
    }
}

// ---------------- readout ----------------
__global__ void k_readout(const float* __restrict__ fcw, const float* __restrict__ fcb,
                          float* __restrict__ out){
    int g = blockIdx.x, t = threadIdx.x;     // 128 threads
    __shared__ float sf[F3];
    __shared__ float slg[10];
    float s = 0.f, cnt = 0.f;
    for (int j = 0; j < 16; j++){
        int n = g*16 + j;
        float nv = d_cnt2[n] > 0.f ? 1.f : 0.f;
        cnt += nv;
        s += nv * d_h3[n*F3 + t];
    }
    sf[t] = s / fmaxf(cnt, 1.f);
    __syncthreads();
    if (t < 10){
        float l = fcb[t];
        for (int i = 0; i < F3; i++) l += sf[i] * fcw[i*10 + t];
        slg[t] = l;
    }
    __syncthreads();
    if (t == 0){
        float mx = slg[0];
        for (int o = 1; o < 10; o++) mx = fmaxf(mx, slg[o]);
        float se = 0.f;
        for (int o = 0; o < 10; o++) se += expf(slg[o] - mx);
        float lse = logf(se) + mx;
        for (int o = 0; o < 10; o++) out[g*10 + o] = slg[o] - lse;
    }
}

// ---------------- launch ----------------
extern "C" void kernel_launch(void* const* d_in, const int* in_sizes, int n_in,
                              void* d_out, int out_size){
    const float* x    = (const float*)d_in[0];
    const float* pos  = (const float*)d_in[1];
    const int*   ei   = (const int*)  d_in[2];
    const float* W1   = (const float*)d_in[4];
    const float* r1   = (const float*)d_in[5];
    const float* b1   = (const float*)d_in[6];
    const float* W2   = (const float*)d_in[7];
    const float* r2p  = (const float*)d_in[8];
    const float* b2   = (const float*)d_in[9];
    const float* W3   = (const float*)d_in[10];
    const float* r3p  = (const float*)d_in[11];
    const float* b3   = (const float*)d_in[12];
    const float* fcw  = (const float*)d_in[13];
    const float* fcb  = (const float*)d_in[14];
    float* out = (float*)d_out;
    const int* row = ei;        // targets
    const int* col = ei + EE;   // sources

    k_init      <<<256, 256>>>();
    k_nbucket   <<<EE/256, 256>>>(row, col);
    k_m1g       <<<BG, 256>>>(pos);
    k_graph1    <<<BG, 256>>>(x, pos, W1, r1, b1);
    k_acc2      <<<BG*8, 256>>>();
    k_gemm2pool <<<dim3(NC1/64, 1), 256>>>(W2, r2p, b2);
    k_fin_x3    <<<NC2*F2/256, 256>>>();
    k_acc3      <<<BG*2, 256>>>();
    k_gemm3     <<<dim3(NC2/64, F3/64), 256>>>(W3, r3p, b3);
    k_readout   <<<BG, 128>>>(fcw, fcb, out);
}

// round 8
// speedup vs baseline: 2.2360x; 1.0295x over previous
#include <cuda_runtime.h>
#include <math.h>

// ---------------- problem constants ----------------
#define BG   256
#define NPG  256
#define NN   (BG*NPG)            // 65536 nodes
#define EE   (NN*16)             // 1048576 edges
#define KK   25
#define F1   32
#define F2   64
#define F3   128
#define NC1  (BG*64)             // 16384 pool-1 clusters
#define NC2  (BG*16)             // 4096  pool-2 clusters
#define NBCAP 64                 // max in-edges per node (avg 16)

// ---------------- device scratch ----------------
__device__ float    d_m[4];
__device__ int      d_ncnt1[NN];
__device__ unsigned char d_nbuf[(size_t)NN*NBCAP];   // 4MB: per-node source bytes
__device__ float    d_x2[NC1*F1];
__device__ float    d_cnt1[NC1];
__device__ float    d_pos2[NC1*2];
__device__ int      d_bcnt2[NC1];
__device__ unsigned char d_bkt2[NC1*64];
__device__ int      d_bcnt3[NC2];
__device__ unsigned char d_bkt3[NC2*16];
__device__ float    d_acc2[(size_t)NC1*KK*F1];  // pre-divided by deg
__device__ float    d_x3[NC2*F2];
__device__ float    d_cnt2[NC2];
__device__ float    d_pos3[NC2*2];
__device__ float    d_acc3[(size_t)NC2*KK*F2];  // pre-divided by deg
__device__ float    d_h3[NC2*F3];

// ---------------- helpers ----------------
__device__ __forceinline__ float eluf(float v){ return v > 0.f ? v : expm1f(v); }

__device__ __forceinline__ void atomicMaxF(float* a, float v){
    if (v >= 0.f) atomicMax((int*)a, __float_as_int(v));
    else          atomicMin((unsigned int*)a, __float_as_uint(v));
}

__device__ __forceinline__ void warpMaxAtomic(float mx, float* dst){
    #pragma unroll
    for (int o = 16; o; o >>= 1) mx = fmaxf(mx, __shfl_xor_sync(0xffffffffu, mx, o));
    if ((threadIdx.x & 31) == 0) atomicMax((int*)dst, __float_as_int(mx));
}

__device__ __forceinline__ void spline_corners(float psx, float psy,
                                               int& ix, int& iy, float& fx, float& fy){
    float vx = psx * 4.f, vy = psy * 4.f;
    float fix = fminf(fmaxf(floorf(vx), 0.f), 3.f);
    float fiy = fminf(fmaxf(floorf(vy), 0.f), 3.f);
    fx = vx - fix; fy = vy - fiy;
    ix = (int)fix; iy = (int)fiy;
}

__device__ __forceinline__ int cell1(float px, float py){
    int cx = min(max((int)floorf(px * 0.25f), 0), 7);
    int cy = min(max((int)floorf(py * 0.25f), 0), 7);
    return cx * 8 + cy;
}
__device__ __forceinline__ int clu2_of(int j){
    float px = d_pos2[2*j], py = d_pos2[2*j+1];
    int cx = min(max((int)floorf(px * 0.125f), 0), 3);
    int cy = min(max((int)floorf(py * 0.125f), 0), 3);
    return (j >> 6) * 16 + cx * 4 + cy;
}

// f32x2 packed FMA helpers
__device__ __forceinline__ unsigned long long splat2(float x){
    unsigned long long r;
    asm("mov.b64 %0, {%1, %1};" : "=l"(r) : "f"(x));
    return r;
}
__device__ __forceinline__ void ffma2(unsigned long long& d,
                                      unsigned long long a, unsigned long long b){
    asm("fma.rn.f32x2 %0, %1, %2, %0;" : "+l"(d) : "l"(a), "l"(b));
}
__device__ __forceinline__ float f2lo(unsigned long long u){ return __uint_as_float((unsigned)u); }
__device__ __forceinline__ float f2hi(unsigned long long u){ return __uint_as_float((unsigned)(u>>32)); }

// ---------------- init ----------------
__global__ void k_init(){
    int t = blockIdx.x*blockDim.x + threadIdx.x;     // 65536
    const float NEG = -3.4e38f;
    ((float4*)d_x3)[t] = make_float4(NEG,NEG,NEG,NEG);   // NC2*F2/4 = 65536
    d_ncnt1[t] = 0;
    if (t < 4) d_m[t] = 0.f;
}

// bucket edges by target node (4 edges per thread)
__global__ void k_nbucket(const int4* __restrict__ row4, const int4* __restrict__ col4){
    int i = blockIdx.x*blockDim.x + threadIdx.x;     // EE/4 threads
    int4 r = row4[i], c = col4[i];
    int s0 = atomicAdd(&d_ncnt1[r.x], 1);
    if (s0 < NBCAP) d_nbuf[(size_t)r.x*NBCAP + s0] = (unsigned char)(c.x & 255);
    int s1 = atomicAdd(&d_ncnt1[r.y], 1);
    if (s1 < NBCAP) d_nbuf[(size_t)r.y*NBCAP + s1] = (unsigned char)(c.y & 255);
    int s2 = atomicAdd(&d_ncnt1[r.z], 1);
    if (s2 < NBCAP) d_nbuf[(size_t)r.z*NBCAP + s2] = (unsigned char)(c.z & 255);
    int s3 = atomicAdd(&d_ncnt1[r.w], 1);
    if (s3 < NBCAP) d_nbuf[(size_t)r.w*NBCAP + s3] = (unsigned char)(c.w & 255);
}

// global pseudo max (level 1) from compact per-node edges; block per graph
__global__ void k_m1g(const float* __restrict__ pos){
    __shared__ float2 ps[NPG];
    int g = blockIdx.x, t = threadIdx.x;
    ps[t] = ((const float2*)pos)[g*NPG + t];
    __syncthreads();
    int gn = g*NPG + t;
    int cnt = min(d_ncnt1[gn], NBCAP);
    const unsigned char* nb = d_nbuf + (size_t)gn*NBCAP;
    float2 mp = ps[t];
    float mx = 0.f;
    for (int e = 0; e < cnt; e++){
        float2 pc = ps[nb[e]];
        mx = fmaxf(mx, fmaxf(fabsf(pc.x - mp.x), fabsf(pc.y - mp.y)));
    }
    warpMaxAtomic(mx, &d_m[0]);
}

// ---------------- mega-kernel: layer1 conv+pool + level2/3 graph build (512 thr) ----------------
__global__ void __launch_bounds__(512) k_graph1(
        const float* __restrict__ x, const float* __restrict__ pos,
        const float* __restrict__ W1, const float* __restrict__ r1,
        const float* __restrict__ b1){
    extern __shared__ float acc_dyn[];     // 512*26 floats = 53.2KB
    __shared__ float  x2_s[64*F1];         // 8KB
    __shared__ unsigned char bkt_s[64*64]; // 4KB
    __shared__ float  W1s[KK*F1];          // 3.2KB
    __shared__ float2 ps[NPG];             // 2KB
    __shared__ float  xs_s[NPG];           // 1KB
    __shared__ unsigned char cell_s[NPG];
    __shared__ unsigned bm_s[128];
    __shared__ int    bcnt_s[64];
    __shared__ float  cnt1_s[64];
    __shared__ float  pos2_s[64*2];
    __shared__ unsigned char cell2_s[64];
    __shared__ unsigned bm3_s[8];
    __shared__ int    bcnt3_s[16];
    __shared__ unsigned char bkt3_s[16*16];
    __shared__ float  cnt2_s[16];
    __shared__ float  pos3_s[16*2];
    __shared__ float  r1s[F1], b1s[F1];

    int g = blockIdx.x, t = threadIdx.x;   // 512 threads
    int half = t >> 8;                      // 0/1
    int n = t & 255;                        // node within graph
    int gn = g*NPG + n;

    // ---- P1: loads + zeroing ----
    float2 myp = ((const float2*)pos)[gn];
    if (half == 0){
        ps[n] = myp;
        xs_s[n] = x[gn];
        cell_s[n] = (unsigned char)cell1(myp.x, myp.y);
    }
    for (int i = t; i < KK*F1; i += 512) W1s[i] = W1[i];
    if (t < F1){ r1s[t] = r1[t]; b1s[t] = b1[t]; }
    #pragma unroll
    for (int k = 0; k < 26; k++) acc_dyn[t*26 + k] = 0.f;
    {
        const float NEG = -3.4e38f;
        for (int i = t; i < 64*F1; i += 512) x2_s[i] = NEG;
    }
    if (t < 128) bm_s[t] = 0u;
    if (t < 64){ bcnt_s[t] = 0; cnt1_s[t] = 0.f; pos2_s[2*t] = 0.f; pos2_s[2*t+1] = 0.f; }
    if (t < 16){ bcnt3_s[t] = 0; cnt2_s[t] = 0.f; pos3_s[2*t] = 0.f; pos3_s[2*t+1] = 0.f; }
    if (t < 8) bm3_s[t] = 0u;
    __syncthreads();

    // ---- P2: per-node edge accumulation (split across thread pair) + level-2 dedup ----
    int rawcnt = d_ncnt1[gn];
    int cnt = min(rawcnt, NBCAP);
    const unsigned char* nb = d_nbuf + (size_t)gn*NBCAP;
    float inv1 = 1.f / (2.f * d_m[0] + 1e-12f);
    float* ar = &acc_dyn[t*26];
    int r2cell = cell_s[n];
    for (int e = half; e < cnt; e += 2){
        int c = nb[e];
        float2 pc = ps[c];
        float psx = (pc.x - myp.x) * inv1 + 0.5f;
        float psy = (pc.y - myp.y) * inv1 + 0.5f;
        int ix, iy; float fx, fy;
        spline_corners(psx, psy, ix, iy, fx, fy);
        float xin = xs_s[c];
        int kb = ix*5 + iy;
        float w00 = (1.f-fx)*(1.f-fy), w01 = (1.f-fx)*fy;
        float w10 = fx*(1.f-fy),       w11 = fx*fy;
        ar[kb  ] += w00 * xin;
        ar[kb+1] += w01 * xin;
        ar[kb+5] += w10 * xin;
        ar[kb+6] += w11 * xin;
        int c2 = cell_s[c];
        if (r2cell != c2){
            int key = r2cell*64 + c2;
            unsigned bit = 1u << (key & 31);
            unsigned old = atomicOr(&bm_s[key >> 5], bit);
            if (!(old & bit)){
                int sl = atomicAdd(&bcnt_s[r2cell], 1);
                bkt_s[r2cell*64 + sl] = (unsigned char)c2;
            }
        }
    }
    __syncthreads();
    // merge the two half-accumulators into rows [0,256)
    if (half == 0){
        #pragma unroll
        for (int k = 0; k < 25; k++) ar[k] += acc_dyn[(t+256)*26 + k];
    }
    __syncthreads();

    // ---- P3: node transform (each thread computes 16 of 32 outputs) + pool-1 ----
    {
        float invd = 1.f / fmaxf((float)rawcnt, 1.f);
        float xn = xs_s[n];
        const float* arn = &acc_dyn[n*26];
        int ob = half*16;
        float h[16];
        #pragma unroll
        for (int j = 0; j < 16; j++) h[j] = b1s[ob+j] + xn * r1s[ob+j];
        #pragma unroll
        for (int k = 0; k < KK; k++){
            float a = arn[k] * invd;
            #pragma unroll
            for (int j = 0; j < 16; j++) h[j] += a * W1s[k*F1 + ob + j];
        }
        int cl = r2cell;
        if (half == 0){
            atomicAdd(&cnt1_s[cl], 1.f);
            atomicAdd(&pos2_s[2*cl],   myp.x);
            atomicAdd(&pos2_s[2*cl+1], myp.y);
        }
        #pragma unroll
        for (int j = 0; j < 16; j++)
            atomicMaxF(&x2_s[cl*F1 + ob + j], eluf(h[j]));
    }
    __syncthreads();

    // ---- P4: finalize clusters ----
    if (t < 64){
        float c = cnt1_s[t];
        float invc = 1.f / fmaxf(c, 1.f);
        float px = pos2_s[2*t] * invc, py = pos2_s[2*t+1] * invc;
        pos2_s[2*t] = px; pos2_s[2*t+1] = py;
        int cx = min(max((int)floorf(px * 0.125f), 0), 3);
        int cy = min(max((int)floorf(py * 0.125f), 0), 3);
        cell2_s[t] = (unsigned char)(cx*4 + cy);
        d_cnt1[g*64 + t] = c;
        d_pos2[(g*64 + t)*2]     = px;
        d_pos2[(g*64 + t)*2 + 1] = py;
        d_bcnt2[g*64 + t] = bcnt_s[t];
    }
    __syncthreads();

    // ---- P5: write x2 (zero empty clusters) + pool-2 meta ----
    for (int i = t; i < 64*F1; i += 512){
        int cl = i >> 5;
        d_x2[g*64*F1 + i] = (cnt1_s[cl] > 0.f) ? x2_s[i] : 0.f;
    }
    if (t < 64 && cnt1_s[t] > 0.f){
        int c2 = cell2_s[t];
        atomicAdd(&cnt2_s[c2], 1.f);
        atomicAdd(&pos3_s[2*c2],   pos2_s[2*t]);
        atomicAdd(&pos3_s[2*c2+1], pos2_s[2*t+1]);
    }
    __syncthreads();

    // ---- P6: finalize pool-2 positions ----
    if (t < 16){
        float c = cnt2_s[t];
        float invc = 1.f / fmaxf(c, 1.f);
        pos3_s[2*t]   *= invc;
        pos3_s[2*t+1] *= invc;
        d_cnt2[g*16 + t] = c;
        d_pos3[(g*16 + t)*2]     = pos3_s[2*t];
        d_pos3[(g*16 + t)*2 + 1] = pos3_s[2*t+1];
    }
    __syncthreads();

    // ---- P7: m2 partial + build level-3 buckets; write level-2 buckets ----
    {
        float mx = 0.f;
        for (int i = t; i < 64*64; i += 512){
            int r = i >> 6, s = i & 63;
            if (s < bcnt_s[r]){
                int c = bkt_s[i];
                float dx = pos2_s[2*c]   - pos2_s[2*r];
                float dy = pos2_s[2*c+1] - pos2_s[2*r+1];
                mx = fmaxf(mx, fmaxf(fabsf(dx), fabsf(dy)));
                int r3 = cell2_s[r], c3 = cell2_s[c];
                if (r3 != c3){
                    int key = r3*16 + c3;
                    unsigned bit = 1u << (key & 31);
                    unsigned old = atomicOr(&bm3_s[key >> 5], bit);
                    if (!(old & bit)){
                        int sl = atomicAdd(&bcnt3_s[r3], 1);
                        bkt3_s[r3*16 + sl] = (unsigned char)c3;
                    }
                }
            }
        }
        warpMaxAtomic(mx, &d_m[1]);
    }
    if (t < 256) ((uint4*)(d_bkt2 + (size_t)g*4096))[t] = ((uint4*)bkt_s)[t];
    __syncthreads();

    // ---- P8: m3 partial; write level-3 buckets ----
    if (t < 256){
        float mx = 0.f;
        int r = t >> 4, s = t & 15;
        if (s < bcnt3_s[r]){
            int c = bkt3_s[t];
            float dx = pos3_s[2*c]   - pos3_s[2*r];
            float dy = pos3_s[2*c+1] - pos3_s[2*r+1];
            mx = fmaxf(fabsf(dx), fabsf(dy));
        }
        warpMaxAtomic(mx, &d_m[2]);
    }
    if (t < 16){
        d_bcnt3[g*16 + t] = bcnt3_s[t];
        ((uint4*)(d_bkt3 + g*256))[t] = ((uint4*)bkt3_s)[t];
    }
}

// acc2[r,k,i] in SMEM; 8 warps/block, one warp per row; pre-divided by deg
__global__ void k_acc2(){
    __shared__ float acc_s[8*KK*F1];     // 25.6 KB
    __shared__ float xs[64*F1];          // 8 KB
    int b = blockIdx.x;                  // 2048 = BG*8
    int g = b >> 3, oct = b & 7;
    int t = threadIdx.x, w = t >> 5, lane = t & 31;
    float4 z4 = make_float4(0,0,0,0);
    for (int i = t; i < 8*KK*F1/4; i += 256) ((float4*)acc_s)[i] = z4;
    for (int i = t; i < 64*F1/4;   i += 256) ((float4*)xs)[i] = ((const float4*)(d_x2 + g*64*F1))[i];
    __syncthreads();

    int r = g*64 + oct*8 + w;
    int cnt = d_bcnt2[r];
    float inv = 1.f / (2.f * d_m[1] + 1e-12f);
    float prx = d_pos2[2*r], pry = d_pos2[2*r+1];
    float* accr = &acc_s[w*KK*F1];
    for (int e = 0; e < cnt; e++){
        int cl = d_bkt2[r*64 + e];
        int c = g*64 + cl;
        float psx = (d_pos2[2*c]   - prx) * inv + 0.5f;
        float psy = (d_pos2[2*c+1] - pry) * inv + 0.5f;
        int ix, iy; float fx, fy;
        spline_corners(psx, psy, ix, iy, fx, fy);
        float xv = xs[cl*F1 + lane];
        int kb = ix*5 + iy;
        float w00 = (1.f-fx)*(1.f-fy), w01 = (1.f-fx)*fy;
        float w10 = fx*(1.f-fy),       w11 = fx*fy;
        accr[(kb  )*F1 + lane] += w00 * xv;
        accr[(kb+1)*F1 + lane] += w01 * xv;
        accr[(kb+5)*F1 + lane] += w10 * xv;
        accr[(kb+6)*F1 + lane] += w11 * xv;
    }
    __syncwarp();
    float invd = 1.f / fmaxf((float)cnt, 1.f);
    size_t rowbase = (size_t)r * (KK*F1);
    #pragma unroll
    for (int k = 0; k < KK; k++)
        d_acc2[rowbase + k*F1 + lane] = accr[k*F1 + lane] * invd;
}

// ---------------- 256-thread f32x2 GEMM: OUT = elu(A@W + XIN@ROOT + BIAS) ----------------
template<int BM, int TMH, int KDIM, int FIN, int NOUT, bool POOL>
__device__ __forceinline__ void gemm_body(
    const float* __restrict__ A, const float* __restrict__ W,
    const float* __restrict__ XIN, const float* __restrict__ ROOT,
    const float* __restrict__ BIAS, float* __restrict__ OUT)
{
    const int BK = 16, TM = 2*TMH;
    const int A4 = BM*BK/4;          // float4 loads for A tile
    __shared__ float As[BK][BM + 4];
    __shared__ float Bs[BK][64];
    int bm = blockIdx.x * BM;
    int bn = blockIdx.y * 64;
    int t  = threadIdx.x;            // 256
    int tx = t & 15, ty = t >> 4;
    unsigned long long acc[TMH][4];
    #pragma unroll
    for (int p=0;p<TMH;p++)
        #pragma unroll
        for (int j=0;j<4;j++) acc[p][j]=0ull;

    const int KTOT = KDIM + FIN;
    for (int kk = 0; kk < KTOT; kk += BK){
        bool ext = (kk >= KDIM);
        const float* srcA = ext ? XIN : A;
        const float* srcB = ext ? ROOT : W;
        int ld   = ext ? FIN : KDIM;
        int kofs = ext ? (kk - KDIM) : kk;
        #pragma unroll
        for (int w = 0; w < (A4 + 255)/256; w++){
            int fidx = t + w*256;
            if ((A4 & 255) == 0 || fidx < A4){
                int idx = fidx * 4;
                int m = idx >> 4, k4 = idx & 15;
                float4 v = *(const float4*)&srcA[(size_t)(bm+m)*ld + kofs + k4];
                As[k4+0][m]=v.x; As[k4+1][m]=v.y; As[k4+2][m]=v.z; As[k4+3][m]=v.w;
            }
        }
        {
            int k = t >> 4, n4 = (t & 15) * 4;
            *(float4*)&Bs[k][n4] = *(const float4*)&srcB[(size_t)(kofs+k)*NOUT + bn + n4];
        }
        __syncthreads();
        #pragma unroll
        for (int kb = 0; kb < BK; kb++){
            unsigned long long a[TMH];
            #pragma unroll
            for (int p=0;p<TMH;p++)
                a[p] = *(const unsigned long long*)&As[kb][ty*TM + 2*p];
            float4 b4 = *(const float4*)&Bs[kb][tx*4];
            unsigned long long b0=splat2(b4.x), b1=splat2(b4.y),
                               b2=splat2(b4.z), b3=splat2(b4.w);
            #pragma unroll
            for (int p=0;p<TMH;p++){
                ffma2(acc[p][0], a[p], b0);
                ffma2(acc[p][1], a[p], b1);
                ffma2(acc[p][2], a[p], b2);
                ffma2(acc[p][3], a[p], b3);
            }
        }
        __syncthreads();
    }
    #pragma unroll
    for (int p = 0; p < TMH; p++){
        int m0 = bm + ty*TM + 2*p;
        int ob = bn + tx*4;
        if (POOL){
            #pragma unroll
            for (int half = 0; half < 2; half++){
                int m = m0 + half;
                if (d_cnt1[m] <= 0.f) continue;
                int cl = clu2_of(m);
                #pragma unroll
                for (int j = 0; j < 4; j++){
                    float v = half ? f2hi(acc[p][j]) : f2lo(acc[p][j]);
                    atomicMaxF(&d_x3[cl*F2 + ob + j], eluf(v + BIAS[ob + j]));
                }
            }
        } else {
            float b0 = BIAS[ob], b1 = BIAS[ob+1], b2 = BIAS[ob+2], b3 = BIAS[ob+3];
            float4 o0 = make_float4(eluf(f2lo(acc[p][0])+b0), eluf(f2lo(acc[p][1])+b1),
                                    eluf(f2lo(acc[p][2])+b2), eluf(f2lo(acc[p][3])+b3));
            float4 o1 = make_float4(eluf(f2hi(acc[p][0])+b0), eluf(f2hi(acc[p][1])+b1),
                                    eluf(f2hi(acc[p][2])+b2), eluf(f2hi(acc[p][3])+b3));
            *(float4*)&OUT[(size_t)m0*NOUT + ob]     = o0;
            *(float4*)&OUT[(size_t)(m0+1)*NOUT + ob] = o1;
        }
    }
}

__global__ void k_gemm2pool(const float* __restrict__ W, const float* __restrict__ ROOT,
                            const float* __restrict__ BIAS){
    gemm_body<64, 2, KK*F1, F1, F2, true>(d_acc2, W, d_x2, ROOT, BIAS, d_x3);
}
__global__ void k_gemm3(const float* __restrict__ W, const float* __restrict__ ROOT,
                        const float* __restrict__ BIAS){
    gemm_body<32, 1, KK*F2, F2, F3, false>(d_acc3, W, d_x3, ROOT, BIAS, d_h3);
}

// acc3 in SMEM; 8 warps/block, warp per row; pre-divided by deg.
// x3 zero-fix for empty clusters applied on SMEM load (replaces k_fin_x3 for the
// accumulation path; gemm3's XIN reads raw x3 but those rows are masked in readout).
__global__ void k_acc3(){
    __shared__ float acc_s[8*KK*F2];     // 51.2 KB
    __shared__ float xs[16*F2];          // 4 KB
    int b = blockIdx.x;                  // 512 = BG*2
    int g = b >> 1, half = b & 1;
    int t = threadIdx.x, w = t >> 5, lane = t & 31;
    float4 z4 = make_float4(0,0,0,0);
    for (int i = t; i < 8*KK*F2/4; i += 256) ((float4*)acc_s)[i] = z4;
    for (int i = t; i < 16*F2/4;   i += 256){
        int cl = i >> 4;                 // 16 float4 per row of F2
        float4 v = ((const float4*)(d_x3 + g*16*F2))[i];
        if (d_cnt2[g*16 + cl] <= 0.f) v = z4;
        ((float4*)xs)[i] = v;
    }
    __syncthreads();

    int r = g*16 + half*8 + w;
    int cnt = d_bcnt3[r];
    float inv = 1.f / (2.f * d_m[2] + 1e-12f);
    float prx = d_pos3[2*r], pry = d_pos3[2*r+1];
    float* accr = &acc_s[w*KK*F2];
    for (int e = 0; e < cnt; e++){
        int cl = d_bkt3[r*16 + e];
        int c = g*16 + cl;
        float psx = (d_pos3[2*c]   - prx) * inv + 0.5f;
        float psy = (d_pos3[2*c+1] - pry) * inv + 0.5f;
        int ix, iy; float fx, fy;
        spline_corners(psx, psy, ix, iy, fx, fy);
        float xv0 = xs[cl*F2 + lane];
        float xv1 = xs[cl*F2 + lane + 32];
        int kb = ix*5 + iy;
        float w00 = (1.f-fx)*(1.f-fy), w01 = (1.f-fx)*fy;
        float w10 = fx*(1.f-fy),       w11 = fx*fy;
        accr[(kb  )*F2 + lane]      += w00 * xv0;
        accr[(kb  )*F2 + lane + 32] += w00 * xv1;
        accr[(kb+1)*F2 + lane]      += w01 * xv0;
        accr[(kb+1)*F2 + lane + 32] += w01 * xv1;
        accr[(kb+5)*F2 + lane]      += w10 * xv0;
        accr[(kb+5)*F2 + lane + 32] += w10 * xv1;
        accr[(kb+6)*F2 + lane]      += w11 * xv0;
        accr[(kb+6)*F2 + lane + 32] += w11 * xv1;
    }
    __syncwarp();
    float invd = 1.f / fmaxf((float)cnt, 1.f);
    size_t rowbase = (size_t)r * (KK*F2);
    #pragma unroll
    for (int k = 0; k < KK; k++){
        d_acc3[rowbase + k*F2 + lane]      = accr[k*F2 + lane]      * invd;
        d_acc3[rowbase + k*F2 + lane + 32] = accr[k*F2 + lane + 32] * invd;
    }
}

// x3 zero-fix for gemm3's XIN path (root term of valid rows is unaffected;
// run before gemm3 so empty-cluster rows don't propagate NEG into h3).
__global__ void k_fin_x3(){
    int t = blockIdx.x*blockDim.x + threadIdx.x;
    if (t >= NC2*F2) return;
    if (d_cnt2[t / F2] <= 0.f) d_x3[t] = 0.f;
}

// ---------------- readout ----------------
__global__ void k_readout(const float* __restrict__ fcw, const float* __restrict__ fcb,
                          float* __restrict__ out){
    int g = blockIdx.x, t = threadIdx.x;     // 128 threads
    __shared__ float sf[F3];
    __shared__ float slg[10];
    float s = 0.f, cnt = 0.f;
    for (int j = 0; j < 16; j++){
        int n = g*16 + j;
        float nv = d_cnt2[n] > 0.f ? 1.f : 0.f;
        cnt += nv;
        s += nv * d_h3[n*F3 + t];
    }
    sf[t] = s / fmaxf(cnt, 1.f);
    __syncthreads();
    if (t < 10){
        float l = fcb[t];
        for (int i = 0; i < F3; i++) l += sf[i] * fcw[i*10 + t];
        slg[t] = l;
    }
    __syncthreads();
    if (t == 0){
        float mx = slg[0];
        for (int o = 1; o < 10; o++) mx = fmaxf(mx, slg[o]);
        float se = 0.f;
        for (int o = 0; o < 10; o++) se += expf(slg[o] - mx);
        float lse = logf(se) + mx;
        for (int o = 0; o < 10; o++) out[g*10 + o] = slg[o] - lse;
    }
}

// ---------------- launch ----------------
extern "C" void kernel_launch(void* const* d_in, const int* in_sizes, int n_in,
                              void* d_out, int out_size){
    const float* x    = (const float*)d_in[0];
    const float* pos  = (const float*)d_in[1];
    const int*   ei   = (const int*)  d_in[2];
    const float* W1   = (const float*)d_in[4];
    const float* r1   = (const float*)d_in[5];
    const float* b1   = (const float*)d_in[6];
    const float* W2   = (const float*)d_in[7];
    const float* r2p  = (const float*)d_in[8];
    const float* b2   = (const float*)d_in[9];
    const float* W3   = (const float*)d_in[10];
    const float* r3p  = (const float*)d_in[11];
    const float* b3   = (const float*)d_in[12];
    const float* fcw  = (const float*)d_in[13];
    const float* fcb  = (const float*)d_in[14];
    float* out = (float*)d_out;
    const int* row = ei;        // targets
    const int* col = ei + EE;   // sources

    const int G1_SMEM = 512*26*4;   // 53248 bytes dynamic
    cudaFuncSetAttribute(k_graph1, cudaFuncAttributeMaxDynamicSharedMemorySize, G1_SMEM);

    k_init      <<<256, 256>>>();
    k_nbucket   <<<EE/1024, 256>>>((const int4*)row, (const int4*)col);
    k_m1g       <<<BG, 256>>>(pos);
    k_graph1    <<<BG, 512, G1_SMEM>>>(x, pos, W1, r1, b1);
    k_acc2      <<<BG*8, 256>>>();
    k_gemm2pool <<<dim3(NC1/64, 1), 256>>>(W2, r2p, b2);
    k_fin_x3    <<<NC2*F2/256, 256>>>();
    k_acc3      <<<BG*2, 256>>>();
    k_gemm3     <<<dim3(NC2/32, F3/64), 256>>>(W3, r3p, b3);
    k_readout   <<<BG, 128>>>(fcw, fcb, out);
}